// round 1
// baseline (speedup 1.0000x reference)
#include <cuda_runtime.h>
#include <math.h>
#include <stdint.h>

#define TT 256
#define BB 256
#define II 256
#define HH 1024
#define BH (BB * HH)

// ----------------- scratch (device globals; no runtime allocation) -----------------
__device__ float g_inp0[(size_t)TT * BB * HH];   // layer0 input projection [T][B][H]
__device__ float g_h1[(size_t)TT * BB * HH];     // layer0 hidden history   [T][B][H]
__device__ float g_inp1[(size_t)TT * BB * HH];   // layer1 input projection [T][B][H]
__device__ float g_hA[BB * HH];                  // layer1 ping
__device__ float g_hB[BB * HH];                  // layer1 pong
__device__ unsigned g_arrive = 0;                // monotonic grid-barrier counter

// ----------------- grid barrier (all CTAs guaranteed resident: 128 <= 148 SMs) -----
__device__ __forceinline__ void grid_barrier_128() {
    __syncthreads();
    if (threadIdx.x == 0) {
        __threadfence();
        unsigned a = atomicAdd(&g_arrive, 1u) + 1u;
        unsigned target = ((a - 1u) / 128u + 1u) * 128u;
        while (*((volatile unsigned*)&g_arrive) < target) { }
        __threadfence();
    }
    __syncthreads();
}

// ----------------- input-projection GEMM -------------------------------------------
// out[m][n] = sum_k A[m][k] * W[n][k] + (bia[n] + bib[n])
// LAYER==0: A = x with m=(t,b) -> x[b][t][:], K=II, out=g_inp0
// LAYER==1: A = g_h1, m direct, K=HH, out=g_inp1
template <int LAYER>
__global__ void __launch_bounds__(256) gemm_in_kernel(
    const float* __restrict__ A, const float* __restrict__ W,
    const float* __restrict__ bia, const float* __restrict__ bib)
{
    constexpr int K  = (LAYER == 0) ? II : HH;
    constexpr int BM = 64, BN = 64, BK = 16;
    __shared__ float as[BM][BK + 4];  // stride 20 floats (80B, 16B-aligned)
    __shared__ float bs[BK][BN];      // transposed W tile: bs[k][n]

    float* outp = (LAYER == 0) ? g_inp0 : g_inp1;

    const int m0 = blockIdx.y * BM;
    const int n0 = blockIdx.x * BN;
    const int tid = threadIdx.x;
    const int rowg = tid >> 3;   // 0..31 -> rows rowg*2, rowg*2+1
    const int colg = tid & 7;    // 0..7  -> cols colg*8 .. +7

    float acc[2][8];
#pragma unroll
    for (int i = 0; i < 2; i++)
#pragma unroll
        for (int j = 0; j < 8; j++) acc[i][j] = 0.f;

    // loader mapping: A tile 64 rows x 16k (one float4 per thread)
    const int lr = tid >> 2;            // 0..63
    const int lk = (tid & 3) << 2;      // 0,4,8,12
    const float* arow;
    if (LAYER == 0) {
        int m = m0 + lr;
        int t = m >> 8;        // B == 256
        int b = m & 255;
        arow = A + ((size_t)b * TT + t) * II;
    } else {
        arow = g_h1 + (size_t)(m0 + lr) * HH;
    }
    const int wc = tid >> 2;            // 0..63 (col of W tile)
    const float* wrow = W + (size_t)(n0 + wc) * K;

    for (int k0 = 0; k0 < K; k0 += BK) {
        __syncthreads();
        float4 av = *(const float4*)(arow + k0 + lk);
        *(float4*)(&as[lr][lk]) = av;
        float4 wv = *(const float4*)(wrow + k0 + lk);
        bs[lk + 0][wc] = wv.x;
        bs[lk + 1][wc] = wv.y;
        bs[lk + 2][wc] = wv.z;
        bs[lk + 3][wc] = wv.w;
        __syncthreads();
#pragma unroll
        for (int kk = 0; kk < BK; ++kk) {
            float a0 = as[rowg * 2 + 0][kk];
            float a1 = as[rowg * 2 + 1][kk];
            float4 b0 = *(const float4*)(&bs[kk][colg * 8]);
            float4 b1 = *(const float4*)(&bs[kk][colg * 8 + 4]);
            acc[0][0] += a0 * b0.x; acc[0][1] += a0 * b0.y;
            acc[0][2] += a0 * b0.z; acc[0][3] += a0 * b0.w;
            acc[0][4] += a0 * b1.x; acc[0][5] += a0 * b1.y;
            acc[0][6] += a0 * b1.z; acc[0][7] += a0 * b1.w;
            acc[1][0] += a1 * b0.x; acc[1][1] += a1 * b0.y;
            acc[1][2] += a1 * b0.z; acc[1][3] += a1 * b0.w;
            acc[1][4] += a1 * b1.x; acc[1][5] += a1 * b1.y;
            acc[1][6] += a1 * b1.z; acc[1][7] += a1 * b1.w;
        }
    }

#pragma unroll
    for (int i = 0; i < 2; i++) {
        int m = m0 + rowg * 2 + i;
        float4 o0, o1;
        int nb = n0 + colg * 8;
        o0.x = acc[i][0] + bia[nb + 0] + bib[nb + 0];
        o0.y = acc[i][1] + bia[nb + 1] + bib[nb + 1];
        o0.z = acc[i][2] + bia[nb + 2] + bib[nb + 2];
        o0.w = acc[i][3] + bia[nb + 3] + bib[nb + 3];
        o1.x = acc[i][4] + bia[nb + 4] + bib[nb + 4];
        o1.y = acc[i][5] + bia[nb + 5] + bib[nb + 5];
        o1.z = acc[i][6] + bia[nb + 6] + bib[nb + 6];
        o1.w = acc[i][7] + bia[nb + 7] + bib[nb + 7];
        *(float4*)(outp + (size_t)m * HH + nb)     = o0;
        *(float4*)(outp + (size_t)m * HH + nb + 4) = o1;
    }
}

// ----------------- persistent recurrent kernel -------------------------------------
// h_t = tanh(inp[t] + h_{t-1} @ W_hh^T)
// 128 CTAs, tile 32(batch) x 64(hcol), K-chunk 32. Grid barrier per step.
template <int LAYER>
__global__ void __launch_bounds__(256) rnn_kernel(const float* __restrict__ W)
{
    constexpr int BM = 32, BN = 64, BK = 32;
    __shared__ float hs[BM][BK + 4];  // stride 36 floats (144B, 16B-aligned)
    __shared__ float ws[BK][BN];      // transposed: ws[k][c] = W[n0+c][k]

    const int blk = blockIdx.x;
    const int mt = blk >> 4;     // 0..7
    const int nt = blk & 15;     // 0..15
    const int m0 = mt * BM;
    const int n0 = nt * BN;
    const int tid = threadIdx.x;
    const int row = tid >> 3;    // 0..31
    const int colg = tid & 7;    // 0..7

    const int hr = tid >> 3;             // h-tile loader: row 0..31
    const int hk = (tid & 7) << 2;       // float4 within BK
    const float* inp = (LAYER == 0) ? g_inp0 : g_inp1;

    for (int t = 0; t < TT; ++t) {
        const float* hp;
        float* hn;
        if (LAYER == 0) {
            hn = g_h1 + (size_t)t * BH;
            hp = t ? (g_h1 + (size_t)(t - 1) * BH) : (const float*)0;
        } else {
            hn = (t & 1) ? g_hB : g_hA;
            hp = t ? ((t & 1) ? g_hA : g_hB) : (const float*)0;
        }

        float acc[8];
#pragma unroll
        for (int j = 0; j < 8; j++) acc[j] = 0.f;

        if (t > 0) {
            const float* hrow = hp + (size_t)(m0 + hr) * HH + hk;
            for (int k0 = 0; k0 < HH; k0 += BK) {
                __syncthreads();
                // h tile: 32 rows x 32 k, one float4/thread, L1-bypass (cross-SM data)
                float4 hv = __ldcg((const float4*)(hrow + k0));
                *(float4*)(&hs[hr][hk]) = hv;
                // W tile: 64 cols x 32 k = 512 float4, two per thread, transpose on store
                {
                    int idx = tid;
                    int c = idx >> 3;
                    int kq = (idx & 7) << 2;
                    float4 wv = *(const float4*)(W + (size_t)(n0 + c) * HH + k0 + kq);
                    ws[kq + 0][c] = wv.x; ws[kq + 1][c] = wv.y;
                    ws[kq + 2][c] = wv.z; ws[kq + 3][c] = wv.w;
                    idx = tid + 256;
                    c = idx >> 3;
                    kq = (idx & 7) << 2;
                    wv = *(const float4*)(W + (size_t)(n0 + c) * HH + k0 + kq);
                    ws[kq + 0][c] = wv.x; ws[kq + 1][c] = wv.y;
                    ws[kq + 2][c] = wv.z; ws[kq + 3][c] = wv.w;
                }
                __syncthreads();
#pragma unroll
                for (int kk = 0; kk < BK; ++kk) {
                    float a = hs[row][kk];
                    float4 b0 = *(const float4*)(&ws[kk][colg * 8]);
                    float4 b1 = *(const float4*)(&ws[kk][colg * 8 + 4]);
                    acc[0] += a * b0.x; acc[1] += a * b0.y;
                    acc[2] += a * b0.z; acc[3] += a * b0.w;
                    acc[4] += a * b1.x; acc[5] += a * b1.y;
                    acc[6] += a * b1.z; acc[7] += a * b1.w;
                }
            }
        }

        // epilogue: add precomputed input, tanh, store
        const float* ip = inp + (size_t)t * BH + (size_t)(m0 + row) * HH + n0 + colg * 8;
        float* op = hn + (size_t)(m0 + row) * HH + n0 + colg * 8;
        float4 i0 = *(const float4*)(ip);
        float4 i1 = *(const float4*)(ip + 4);
        float4 o0, o1;
        o0.x = tanhf(acc[0] + i0.x); o0.y = tanhf(acc[1] + i0.y);
        o0.z = tanhf(acc[2] + i0.z); o0.w = tanhf(acc[3] + i0.w);
        o1.x = tanhf(acc[4] + i1.x); o1.y = tanhf(acc[5] + i1.y);
        o1.z = tanhf(acc[6] + i1.z); o1.w = tanhf(acc[7] + i1.w);
        *(float4*)(op)     = o0;
        *(float4*)(op + 4) = o1;

        grid_barrier_128();
    }
}

// ----------------- final FC + ReLU --------------------------------------------------
__global__ void __launch_bounds__(256) fc_kernel(
    const float* __restrict__ fcW, const float* __restrict__ fcb,
    float* __restrict__ out)
{
    const int b = blockIdx.x;
    const float* h = g_hB + (size_t)b * HH;  // T-1 = 255 is odd -> final state in g_hB
    const int tid = threadIdx.x;
    float s = 0.f;
    for (int i = tid; i < HH; i += 256) s += h[i] * fcW[i];
#pragma unroll
    for (int o = 16; o; o >>= 1) s += __shfl_xor_sync(0xFFFFFFFFu, s, o);
    __shared__ float red[8];
    if ((tid & 31) == 0) red[tid >> 5] = s;
    __syncthreads();
    if (tid == 0) {
        float tot = 0.f;
#pragma unroll
        for (int i = 0; i < 8; i++) tot += red[i];
        out[b] = fmaxf(tot + fcb[0], 0.f);
    }
}

// ----------------- launch -----------------------------------------------------------
extern "C" void kernel_launch(void* const* d_in, const int* in_sizes, int n_in,
                              void* d_out, int out_size)
{
    const float* x     = (const float*)d_in[0];
    const float* W_ih0 = (const float*)d_in[1];
    const float* W_hh0 = (const float*)d_in[2];
    const float* b_ih0 = (const float*)d_in[3];
    const float* b_hh0 = (const float*)d_in[4];
    const float* W_ih1 = (const float*)d_in[5];
    const float* W_hh1 = (const float*)d_in[6];
    const float* b_ih1 = (const float*)d_in[7];
    const float* b_hh1 = (const float*)d_in[8];
    const float* fc_W  = (const float*)d_in[9];
    const float* fc_b  = (const float*)d_in[10];
    float* out = (float*)d_out;

    dim3 ggrid(HH / 64, (TT * BB) / 64);  // (16, 1024)
    gemm_in_kernel<0><<<ggrid, 256>>>(x, W_ih0, b_ih0, b_hh0);
    rnn_kernel<0><<<128, 256>>>(W_hh0);
    gemm_in_kernel<1><<<ggrid, 256>>>(nullptr, W_ih1, b_ih1, b_hh1);
    rnn_kernel<1><<<128, 256>>>(W_hh1);
    fc_kernel<<<BB, 256>>>(fc_W, fc_b, out);
}

// round 4
// speedup vs baseline: 6.7672x; 6.7672x over previous
#include <cuda_runtime.h>
#include <cuda_bf16.h>
#include <math.h>
#include <stdint.h>

#define TT 256
#define BB 256
#define II 256
#define HH 1024
#define BH (BB * HH)

// ----------------- scratch (device globals; no runtime allocation) -----------------
__device__ float g_inp0[(size_t)TT * BB * HH];       // layer0 preact input [T][B][H] fp32
__device__ float g_inp1[(size_t)TT * BB * HH];       // layer1 preact input [T][B][H] fp32
__device__ __nv_bfloat16 g_hist_h[(size_t)TT * BB * HH];  // layer0 h history hi
__device__ __nv_bfloat16 g_hist_l[(size_t)TT * BB * HH];  // layer0 h history lo
__device__ __nv_bfloat16 g_xh[(size_t)TT * BB * II];      // x (transposed to [t*B+b][i]) hi
__device__ __nv_bfloat16 g_xl[(size_t)TT * BB * II];      // x lo
__device__ __nv_bfloat16 g_w0h[HH * II];                  // W_ih0 hi
__device__ __nv_bfloat16 g_w0l[HH * II];
__device__ __nv_bfloat16 g_w1h[HH * HH];                  // W_ih1 hi
__device__ __nv_bfloat16 g_w1l[HH * HH];
__device__ __nv_bfloat16 g_hh[2][BH];                     // layer1 h ping-pong hi
__device__ __nv_bfloat16 g_hl[2][BH];                     // layer1 h ping-pong lo
__device__ unsigned g_arrive = 0;

// ----------------- grid barrier (128 CTAs, all resident at 1 CTA/SM) ---------------
#define GBN 128u
__device__ __forceinline__ void grid_barrier() {
    __syncthreads();
    if (threadIdx.x == 0) {
        __threadfence();
        unsigned a = atomicAdd(&g_arrive, 1u) + 1u;
        unsigned target = ((a - 1u) / GBN + 1u) * GBN;
        while (*((volatile unsigned*)&g_arrive) < target) { }
        __threadfence();
    }
    __syncthreads();
}

// ----------------- portable (sm_80+) asm helpers ------------------------------------
__device__ __forceinline__ uint32_t smem_u32(const void* p) {
    uint32_t a;
    asm("{ .reg .u64 t; cvta.to.shared.u64 t, %1; cvt.u32.u64 %0, t; }" : "=r"(a) : "l"(p));
    return a;
}
__device__ __forceinline__ void cp16(uint32_t dst, const void* src) {
    asm volatile("cp.async.cg.shared.global [%0], [%1], 16;" :: "r"(dst), "l"(src));
}
#define CP_COMMIT() asm volatile("cp.async.commit_group;" ::: "memory")
#define CP_WAIT(n)  asm volatile("cp.async.wait_group %0;" :: "n"(n) : "memory")

__device__ __forceinline__ void ldsm4(uint32_t* r, uint32_t a) {
    asm volatile("ldmatrix.sync.aligned.m8n8.x4.shared.b16 {%0,%1,%2,%3}, [%4];"
                 : "=r"(r[0]), "=r"(r[1]), "=r"(r[2]), "=r"(r[3]) : "r"(a));
}
__device__ __forceinline__ void mma16816(float* d, const uint32_t* a, uint32_t b0, uint32_t b1) {
    asm volatile(
        "mma.sync.aligned.m16n8k16.row.col.f32.bf16.bf16.f32 "
        "{%0,%1,%2,%3}, {%4,%5,%6,%7}, {%8,%9}, {%0,%1,%2,%3};"
        : "+f"(d[0]), "+f"(d[1]), "+f"(d[2]), "+f"(d[3])
        : "r"(a[0]), "r"(a[1]), "r"(a[2]), "r"(a[3]), "r"(b0), "r"(b1));
}

// split two fp32 into packed bf16 hi pair + lo pair
__device__ __forceinline__ void split2(float a, float b, uint32_t& hi, uint32_t& lo) {
    __nv_bfloat16 ah = __float2bfloat16_rn(a);
    __nv_bfloat16 bh = __float2bfloat16_rn(b);
    __nv_bfloat16 al = __float2bfloat16_rn(a - __bfloat162float(ah));
    __nv_bfloat16 bl = __float2bfloat16_rn(b - __bfloat162float(bh));
    hi = (uint32_t)__bfloat16_as_ushort(ah) | ((uint32_t)__bfloat16_as_ushort(bh) << 16);
    lo = (uint32_t)__bfloat16_as_ushort(al) | ((uint32_t)__bfloat16_as_ushort(bl) << 16);
}

// ----------------- conversion kernels ------------------------------------------------
// x[b][t][i] fp32 -> g_xh/g_xl[(t*B+b)][i] bf16 hi/lo
__global__ void __launch_bounds__(256) conv_x(const float* __restrict__ x) {
    int idx = blockIdx.x * 256 + threadIdx.x;      // one float4
    int i4  = idx & (II / 4 - 1);
    int rem = idx >> 6;                             // b*TT + t
    int t = rem & (TT - 1);
    int b = rem >> 8;
    float4 v = ((const float4*)x)[idx];
    uint32_t h0, l0, h1, l1;
    split2(v.x, v.y, h0, l0);
    split2(v.z, v.w, h1, l1);
    size_t o = ((size_t)t * BB + b) * II + i4 * 4;
    *(uint2*)&g_xh[o] = make_uint2(h0, h1);
    *(uint2*)&g_xl[o] = make_uint2(l0, l1);
}

// W (row-major [n][k]) fp32 -> hi/lo, same layout. LAYER selects destination.
template <int LAYER>
__global__ void __launch_bounds__(256) conv_w(const float* __restrict__ w, int n4) {
    int idx = blockIdx.x * 256 + threadIdx.x;
    if (idx >= n4) return;
    __nv_bfloat16* dh = (LAYER == 0) ? g_w0h : g_w1h;
    __nv_bfloat16* dl = (LAYER == 0) ? g_w0l : g_w1l;
    float4 v = ((const float4*)w)[idx];
    uint32_t h0, l0, h1, l1;
    split2(v.x, v.y, h0, l0);
    split2(v.z, v.w, h1, l1);
    *(uint2*)&dh[(size_t)idx * 4] = make_uint2(h0, h1);
    *(uint2*)&dl[(size_t)idx * 4] = make_uint2(l0, l1);
}

// ----------------- input-projection GEMM (HMMA, bf16x3) ------------------------------
// out[m][n] = sum_k A[m][k]*W[n][k] + bia[n]+bib[n], M=65536, N=1024
// CTA 128m x 64n, BK=32, 8 warps (4m x 2n), warp 32x32.
// smem per buffer: AsH 10240 | AsL 10240 | BsH 5120 | BsL 5120 = 30720; 2 buffers.
#define GM_BUF 30720
#define GM_SMEM (2 * GM_BUF)

template <int LAYER>
__global__ void __launch_bounds__(256) gemm_bf16(
    const float* __restrict__ bia, const float* __restrict__ bib)
{
    constexpr int KD = (LAYER == 0) ? II : HH;
    extern __shared__ char sm[];
    const uint32_t smb = smem_u32(sm);
    const int tid = threadIdx.x, wid = tid >> 5, l = tid & 31;
    const int m0 = blockIdx.y * 128, n0 = blockIdx.x * 64;
    const int wm = (wid >> 1) * 32, wn = (wid & 1) * 32;

    const __nv_bfloat16* Ah = (LAYER == 0) ? g_xh : g_hist_h;
    const __nv_bfloat16* Al = (LAYER == 0) ? g_xl : g_hist_l;
    const __nv_bfloat16* Wh = (LAYER == 0) ? g_w0h : g_w1h;
    const __nv_bfloat16* Wl = (LAYER == 0) ? g_w0l : g_w1l;
    float* outp = (LAYER == 0) ? g_inp0 : g_inp1;

    // loader mapping
    const int ar = tid >> 1, ahalf = tid & 1;     // A: 128 rows, 2 threads/row (32B each)
    const int br = tid >> 2, bq = tid & 3;        // B: 64 rows, 4 threads/row (16B each)
    const __nv_bfloat16* gAh = Ah + (size_t)(m0 + ar) * KD + ahalf * 16;
    const __nv_bfloat16* gAl = Al + (size_t)(m0 + ar) * KD + ahalf * 16;
    const __nv_bfloat16* gWh = Wh + (size_t)(n0 + br) * KD + bq * 8;
    const __nv_bfloat16* gWl = Wl + (size_t)(n0 + br) * KD + bq * 8;
    const uint32_t dA = smb + (uint32_t)ar * 80 + ahalf * 32;
    const uint32_t dB = smb + 20480 + (uint32_t)br * 80 + bq * 16;

    float acc[2][4][4];
#pragma unroll
    for (int a = 0; a < 2; a++)
#pragma unroll
        for (int b = 0; b < 4; b++)
#pragma unroll
            for (int c = 0; c < 4; c++) acc[a][b][c] = 0.f;

    const uint32_t aFragOff = (uint32_t)(wm + (l & 15)) * 80 + (l >> 4) * 16;
    const int nloc = wn + (l & 7) + ((l >> 4) << 3);
    const uint32_t bFragOff = (uint32_t)nloc * 80 + ((l >> 3) & 1) * 16;

    constexpr int NC = KD / 32;
    // stage chunk 0
    {
        cp16(dA, gAh); cp16(dA + 16, gAh + 8);
        cp16(dA + 10240, gAl); cp16(dA + 10240 + 16, gAl + 8);
        cp16(dB, gWh); cp16(dB + 5120, gWl);
        CP_COMMIT();
    }
    for (int kc = 0; kc < NC; ++kc) {
        const int buf = kc & 1;
        if (kc + 1 < NC) {
            uint32_t o = ((kc + 1) & 1) * GM_BUF;
            cp16(dA + o, gAh + (kc + 1) * 32); cp16(dA + o + 16, gAh + (kc + 1) * 32 + 8);
            cp16(dA + o + 10240, gAl + (kc + 1) * 32); cp16(dA + o + 10240 + 16, gAl + (kc + 1) * 32 + 8);
            cp16(dB + o, gWh + (kc + 1) * 32); cp16(dB + o + 5120, gWl + (kc + 1) * 32);
            CP_COMMIT();
            CP_WAIT(1);
        } else {
            CP_WAIT(0);
        }
        __syncthreads();
        const uint32_t base = smb + buf * GM_BUF;
#pragma unroll
        for (int kk = 0; kk < 2; ++kk) {
            uint32_t bh[2][4], bl[2][4];
#pragma unroll
            for (int nc = 0; nc < 2; ++nc) {
                ldsm4(bh[nc], base + 20480 + bFragOff + nc * (16 * 80) + kk * 32);
                ldsm4(bl[nc], base + 25600 + bFragOff + nc * (16 * 80) + kk * 32);
            }
#pragma unroll
            for (int mc = 0; mc < 2; ++mc) {
                uint32_t ah[4], al[4];
                ldsm4(ah, base + aFragOff + mc * (16 * 80) + kk * 32);
                ldsm4(al, base + 10240 + aFragOff + mc * (16 * 80) + kk * 32);
#pragma unroll
                for (int nc = 0; nc < 2; ++nc) {
                    mma16816(acc[mc][nc * 2 + 0], ah, bh[nc][0], bh[nc][1]);
                    mma16816(acc[mc][nc * 2 + 1], ah, bh[nc][2], bh[nc][3]);
                    mma16816(acc[mc][nc * 2 + 0], ah, bl[nc][0], bl[nc][1]);
                    mma16816(acc[mc][nc * 2 + 1], ah, bl[nc][2], bl[nc][3]);
                    mma16816(acc[mc][nc * 2 + 0], al, bh[nc][0], bh[nc][1]);
                    mma16816(acc[mc][nc * 2 + 1], al, bh[nc][2], bh[nc][3]);
                }
            }
        }
        __syncthreads();
    }

    // epilogue: D layout: d0,d1 -> row l/4, cols (l&3)*2 +0,1; d2,d3 -> row +8
#pragma unroll
    for (int mc = 0; mc < 2; ++mc) {
        int r0 = m0 + wm + mc * 16 + (l >> 2);
#pragma unroll
        for (int f = 0; f < 4; ++f) {
            int c = n0 + wn + f * 8 + (l & 3) * 2;
            float bs0 = bia[c] + bib[c];
            float bs1 = bia[c + 1] + bib[c + 1];
            float2 v0 = make_float2(acc[mc][f][0] + bs0, acc[mc][f][1] + bs1);
            float2 v1 = make_float2(acc[mc][f][2] + bs0, acc[mc][f][3] + bs1);
            *(float2*)&outp[(size_t)r0 * HH + c] = v0;
            *(float2*)&outp[(size_t)(r0 + 8) * HH + c] = v1;
        }
    }
}

// ----------------- persistent HMMA recurrent kernel ---------------------------------
// h_t = tanh(inp[t] + h_{t-1} @ W^T). 128 CTAs = 4 m-tiles(64) x 32 n-tiles(32).
// W slice [32n][1024k] hi/lo persistent in smem (stride 2064B, conflict-free ldsm).
// A (h_{t-1}) staged per step in 16 chunks of K=64 (double-buffered cp.async).
// A chunk row = 64 k * 2B = 128B; 4 threads/row x 32B covers it (FIX for R3 bug).
#define RN_WHI 0
#define RN_WLO 66048
#define RN_A   132096
#define RN_ABUF 18432   /* hi 9216 + lo 9216 */
#define RN_SMEM (RN_A + 2 * RN_ABUF)   /* 168960 */

template <int LAYER>
__global__ void __launch_bounds__(256, 1) rnn_tc(const float* __restrict__ W)
{
    extern __shared__ char sm[];
    const uint32_t smb = smem_u32(sm);
    const int tid = threadIdx.x, wid = tid >> 5, l = tid & 31;
    const int mt = blockIdx.x >> 5;   // 0..3
    const int nt = blockIdx.x & 31;   // 0..31
    const int m0 = mt * 64, n0 = nt * 32;
    const int wm = (wid >> 1) * 16, wn = (wid & 1) * 16;

    // --- W preload: fp32 -> bf16 hi/lo into padded smem [n][k], stride 2064B ---
    for (int i = tid; i < 8192; i += 256) {
        int e = i * 4;
        int n = e >> 10;
        int k = e & 1023;
        float4 w4 = *(const float4*)&W[(size_t)(n0 + n) * HH + k];
        uint32_t h0, l0, h1, l1;
        split2(w4.x, w4.y, h0, l0);
        split2(w4.z, w4.w, h1, l1);
        uint32_t off = (uint32_t)n * 2064 + (uint32_t)k * 2;
        *(uint2*)(sm + RN_WHI + off) = make_uint2(h0, h1);
        *(uint2*)(sm + RN_WLO + off) = make_uint2(l0, l1);
    }
    __syncthreads();

    // fragment addresses
    const uint32_t aRowOff = (uint32_t)(wm + (l & 15)) * 144 + (uint32_t)(l >> 4) * 16;
    const int nloc = wn + (l & 7) + ((l >> 4) << 3);
    const uint32_t bOffH = smb + RN_WHI + (uint32_t)nloc * 2064 + ((l >> 3) & 1) * 16;
    const uint32_t bOffL = smb + RN_WLO + (uint32_t)nloc * 2064 + ((l >> 3) & 1) * 16;

    // A staging mapping: 64 rows, 4 threads/row, each thread 32B (2x cp16) per half
    const int sr = tid >> 2, sq = tid & 3;
    const uint32_t sdst = smb + RN_A + (uint32_t)sr * 144 + (uint32_t)sq * 32;

    const float* inp = (LAYER == 0) ? g_inp0 : g_inp1;

    for (int t = 0; t < TT; ++t) {
        float acc[2][4];
#pragma unroll
        for (int a = 0; a < 2; a++)
#pragma unroll
            for (int b = 0; b < 4; b++) acc[a][b] = 0.f;

        if (t > 0) {
            const __nv_bfloat16 *srcH, *srcL;
            if (LAYER == 0) {
                srcH = g_hist_h + (size_t)(t - 1) * BH;
                srcL = g_hist_l + (size_t)(t - 1) * BH;
            } else {
                int rb = 1 - (t & 1);
                srcH = g_hh[rb];
                srcL = g_hl[rb];
            }
            const __nv_bfloat16* gH = srcH + (size_t)(m0 + sr) * HH + sq * 16;
            const __nv_bfloat16* gL = srcL + (size_t)(m0 + sr) * HH + sq * 16;

            // stage chunk 0
            cp16(sdst, gH);          cp16(sdst + 16, gH + 8);
            cp16(sdst + 9216, gL);   cp16(sdst + 9216 + 16, gL + 8);
            CP_COMMIT();

            for (int kc = 0; kc < 16; ++kc) {
                const int buf = kc & 1;
                if (kc < 15) {
                    uint32_t d = sdst + ((kc + 1) & 1) * RN_ABUF;
                    const __nv_bfloat16* pH = gH + (kc + 1) * 64;
                    const __nv_bfloat16* pL = gL + (kc + 1) * 64;
                    cp16(d, pH);          cp16(d + 16, pH + 8);
                    cp16(d + 9216, pL);   cp16(d + 9216 + 16, pL + 8);
                    CP_COMMIT();
                    CP_WAIT(1);
                } else {
                    CP_WAIT(0);
                }
                __syncthreads();
                const uint32_t aH = smb + RN_A + buf * RN_ABUF + aRowOff;
                const uint32_t aL = aH + 9216;
#pragma unroll
                for (int kk = 0; kk < 4; ++kk) {
                    const int kg = kc * 4 + kk;
                    uint32_t ah[4], al[4], bh[4], bl[4];
                    ldsm4(ah, aH + kk * 32);
                    ldsm4(al, aL + kk * 32);
                    ldsm4(bh, bOffH + kg * 32);
                    ldsm4(bl, bOffL + kg * 32);
                    mma16816(acc[0], ah, bh[0], bh[1]);
                    mma16816(acc[1], ah, bh[2], bh[3]);
                    mma16816(acc[0], ah, bl[0], bl[1]);
                    mma16816(acc[1], ah, bl[2], bl[3]);
                    mma16816(acc[0], al, bh[0], bh[1]);
                    mma16816(acc[1], al, bh[2], bh[3]);
                }
                __syncthreads();
            }
        }

        // --- epilogue: v = tanh(acc + inp[t]); write bf16 hi/lo state ---
        {
            const float* ipb = inp + (size_t)t * BH;
            const int r0 = m0 + wm + (l >> 2);
#pragma unroll
            for (int nc = 0; nc < 2; ++nc) {
                const int c = n0 + wn + nc * 8 + (l & 3) * 2;
#pragma unroll
                for (int hrow = 0; hrow < 2; ++hrow) {
                    const int r = r0 + hrow * 8;
                    float2 ip = *(const float2*)&ipb[(size_t)r * HH + c];
                    float v0 = tanhf(acc[nc][hrow * 2 + 0] + ip.x);
                    float v1 = tanhf(acc[nc][hrow * 2 + 1] + ip.y);
                    uint32_t hi, lo;
                    split2(v0, v1, hi, lo);
                    const size_t oidx = (size_t)r * HH + c;
                    if (LAYER == 0) {
                        *(uint32_t*)&g_hist_h[(size_t)t * BH + oidx] = hi;
                        *(uint32_t*)&g_hist_l[(size_t)t * BH + oidx] = lo;
                    } else {
                        *(uint32_t*)&g_hh[t & 1][oidx] = hi;
                        *(uint32_t*)&g_hl[t & 1][oidx] = lo;
                    }
                }
            }
        }
        grid_barrier();
    }
}

// ----------------- final FC + ReLU ---------------------------------------------------
__global__ void __launch_bounds__(256) fc_kernel(
    const float* __restrict__ fcW, const float* __restrict__ fcb,
    float* __restrict__ out)
{
    const int b = blockIdx.x;
    const int tid = threadIdx.x;
    // final h: t=255 -> buffer (255 & 1) = 1
    const __nv_bfloat16* hh = &g_hh[1][(size_t)b * HH];
    const __nv_bfloat16* hl = &g_hl[1][(size_t)b * HH];
    float s = 0.f;
    for (int i = tid; i < HH; i += 256) {
        float h = __bfloat162float(hh[i]) + __bfloat162float(hl[i]);
        s += h * fcW[i];
    }
#pragma unroll
    for (int o = 16; o; o >>= 1) s += __shfl_xor_sync(0xFFFFFFFFu, s, o);
    __shared__ float red[8];
    if ((tid & 31) == 0) red[tid >> 5] = s;
    __syncthreads();
    if (tid == 0) {
        float tot = 0.f;
#pragma unroll
        for (int i = 0; i < 8; i++) tot += red[i];
        out[b] = fmaxf(tot + fcb[0], 0.f);
    }
}

// ----------------- launch ------------------------------------------------------------
extern "C" void kernel_launch(void* const* d_in, const int* in_sizes, int n_in,
                              void* d_out, int out_size)
{
    const float* x     = (const float*)d_in[0];
    const float* W_ih0 = (const float*)d_in[1];
    const float* W_hh0 = (const float*)d_in[2];
    const float* b_ih0 = (const float*)d_in[3];
    const float* b_hh0 = (const float*)d_in[4];
    const float* W_ih1 = (const float*)d_in[5];
    const float* W_hh1 = (const float*)d_in[6];
    const float* b_ih1 = (const float*)d_in[7];
    const float* b_hh1 = (const float*)d_in[8];
    const float* fc_W  = (const float*)d_in[9];
    const float* fc_b  = (const float*)d_in[10];
    float* out = (float*)d_out;

    cudaFuncSetAttribute(gemm_bf16<0>, cudaFuncAttributeMaxDynamicSharedMemorySize, GM_SMEM);
    cudaFuncSetAttribute(gemm_bf16<1>, cudaFuncAttributeMaxDynamicSharedMemorySize, GM_SMEM);
    cudaFuncSetAttribute(rnn_tc<0>, cudaFuncAttributeMaxDynamicSharedMemorySize, RN_SMEM);
    cudaFuncSetAttribute(rnn_tc<1>, cudaFuncAttributeMaxDynamicSharedMemorySize, RN_SMEM);

    // conversions
    conv_x<<<(TT * BB * II / 4) / 256, 256>>>(x);
    conv_w<0><<<(HH * II / 4 + 255) / 256, 256>>>(W_ih0, HH * II / 4);
    conv_w<1><<<(HH * HH / 4 + 255) / 256, 256>>>(W_ih1, HH * HH / 4);

    dim3 ggrid(HH / 64, (TT * BB) / 128);  // (16, 512)
    gemm_bf16<0><<<ggrid, 256, GM_SMEM>>>(b_ih0, b_hh0);
    rnn_tc<0><<<128, 256, RN_SMEM>>>(W_hh0);
    gemm_bf16<1><<<ggrid, 256, GM_SMEM>>>(b_ih1, b_hh1);
    rnn_tc<1><<<128, 256, RN_SMEM>>>(W_hh1);
    fc_kernel<<<BB, 256>>>(fc_W, fc_b, out);
}

// round 5
// speedup vs baseline: 10.3962x; 1.5363x over previous
#include <cuda_runtime.h>
#include <cuda_fp16.h>
#include <math.h>
#include <stdint.h>

#define TT 256
#define BB 256
#define II 256
#define HH 1024
#define BH (BB * HH)

// ----------------- scratch (device globals; no runtime allocation) -----------------
__device__ float  g_inp0[(size_t)TT * BB * HH];      // layer0 preact [T][B][H] fp32
__device__ float  g_inp1[(size_t)TT * BB * HH];      // layer1 preact [T][B][H] fp32
__device__ __half g_x[(size_t)TT * BB * II];         // x transposed [(t*B+b)][i] fp16
__device__ __half g_hist[(size_t)TT * BB * HH];      // layer0 h history fp16
__device__ __half g_w0h[HH * II];                    // W_ih0 hi fp16
__device__ __half g_w0l[HH * II];                    // W_ih0 lo fp16
__device__ __half g_w1h[(size_t)HH * HH];            // W_ih1 hi
__device__ __half g_w1l[(size_t)HH * HH];            // W_ih1 lo
__device__ __half g_h[2][BH];                        // layer1 h ping-pong fp16
__device__ unsigned g_arrive = 0;

// ----------------- grid barrier (128 CTAs, all resident at 1 CTA/SM) ---------------
#define GBN 128u
__device__ __forceinline__ void grid_barrier() {
    __syncthreads();
    if (threadIdx.x == 0) {
        __threadfence();
        unsigned a = atomicAdd(&g_arrive, 1u) + 1u;
        unsigned target = ((a - 1u) / GBN + 1u) * GBN;
        while (*((volatile unsigned*)&g_arrive) < target) { }
        __threadfence();
    }
    __syncthreads();
}

// ----------------- portable (sm_80+) asm helpers ------------------------------------
__device__ __forceinline__ uint32_t smem_u32(const void* p) {
    uint32_t a;
    asm("{ .reg .u64 t; cvta.to.shared.u64 t, %1; cvt.u32.u64 %0, t; }" : "=r"(a) : "l"(p));
    return a;
}
__device__ __forceinline__ void cp16(uint32_t dst, const void* src) {
    asm volatile("cp.async.cg.shared.global [%0], [%1], 16;" :: "r"(dst), "l"(src));
}
#define CP_COMMIT() asm volatile("cp.async.commit_group;" ::: "memory")
#define CP_WAIT(n)  asm volatile("cp.async.wait_group %0;" :: "n"(n) : "memory")

__device__ __forceinline__ void ldsm4(uint32_t* r, uint32_t a) {
    asm volatile("ldmatrix.sync.aligned.m8n8.x4.shared.b16 {%0,%1,%2,%3}, [%4];"
                 : "=r"(r[0]), "=r"(r[1]), "=r"(r[2]), "=r"(r[3]) : "r"(a));
}
__device__ __forceinline__ void mma16816(float* d, const uint32_t* a, uint32_t b0, uint32_t b1) {
    asm volatile(
        "mma.sync.aligned.m16n8k16.row.col.f32.f16.f16.f32 "
        "{%0,%1,%2,%3}, {%4,%5,%6,%7}, {%8,%9}, {%0,%1,%2,%3};"
        : "+f"(d[0]), "+f"(d[1]), "+f"(d[2]), "+f"(d[3])
        : "r"(a[0]), "r"(a[1]), "r"(a[2]), "r"(a[3]), "r"(b0), "r"(b1));
}

__device__ __forceinline__ uint32_t pack_h2(float a, float b) {
    __half2 h = __floats2half2_rn(a, b);
    return *(uint32_t*)&h;
}
// split two fp32 into packed fp16 hi pair + lo pair
__device__ __forceinline__ void split2h(float a, float b, uint32_t& hi, uint32_t& lo) {
    __half ah = __float2half_rn(a), bh = __float2half_rn(b);
    float ra = a - __half2float(ah), rb = b - __half2float(bh);
    hi = (uint32_t)__half_as_ushort(ah) | ((uint32_t)__half_as_ushort(bh) << 16);
    __half al = __float2half_rn(ra), bl = __float2half_rn(rb);
    lo = (uint32_t)__half_as_ushort(al) | ((uint32_t)__half_as_ushort(bl) << 16);
}

// ----------------- conversion kernels ------------------------------------------------
// x[b][t][i] fp32 -> g_x[(t*B+b)][i] fp16
__global__ void __launch_bounds__(256) conv_x(const float* __restrict__ x) {
    int idx = blockIdx.x * 256 + threadIdx.x;      // one float4
    int i4  = idx & (II / 4 - 1);
    int rem = idx >> 6;                             // b*TT + t
    int t = rem & (TT - 1);
    int b = rem >> 8;
    float4 v = ((const float4*)x)[idx];
    uint32_t p0 = pack_h2(v.x, v.y);
    uint32_t p1 = pack_h2(v.z, v.w);
    *(uint2*)&g_x[((size_t)t * BB + b) * II + i4 * 4] = make_uint2(p0, p1);
}

// W (row-major [n][k]) fp32 -> fp16 hi/lo
template <int LAYER>
__global__ void __launch_bounds__(256) conv_w(const float* __restrict__ w, int n4) {
    int idx = blockIdx.x * 256 + threadIdx.x;
    if (idx >= n4) return;
    __half* dh = (LAYER == 0) ? g_w0h : g_w1h;
    __half* dl = (LAYER == 0) ? g_w0l : g_w1l;
    float4 v = ((const float4*)w)[idx];
    uint32_t h0, l0, h1, l1;
    split2h(v.x, v.y, h0, l0);
    split2h(v.z, v.w, h1, l1);
    *(uint2*)&dh[(size_t)idx * 4] = make_uint2(h0, h1);
    *(uint2*)&dl[(size_t)idx * 4] = make_uint2(l0, l1);
}

// ----------------- input-projection GEMM (HMMA fp16, 2-term: A*(Wh) + A*(Wl)) -------
// out[m][n] = sum_k A[m][k]*W[n][k] + bia[n]+bib[n], M=65536, N=1024
// CTA 128m x 64n, BK=32, 8 warps (4m x 2n), warp 32x32, 3-stage cp.async.
// stage buffer: A [128][80B]=10240 | Bh [64][80]=5120 | Bl 5120 -> 20480
#define GM_BUF 20480
#define GM_SMEM (3 * GM_BUF)

template <int LAYER>
__global__ void __launch_bounds__(256) gemm_f16(
    const float* __restrict__ bia, const float* __restrict__ bib)
{
    constexpr int KD = (LAYER == 0) ? II : HH;
    constexpr int NC = KD / 32;
    extern __shared__ char sm[];
    const uint32_t smb = smem_u32(sm);
    const int tid = threadIdx.x, wid = tid >> 5, l = tid & 31;
    const int m0 = blockIdx.y * 128, n0 = blockIdx.x * 64;
    const int wm = (wid >> 1) * 32, wn = (wid & 1) * 32;

    const __half* A  = (LAYER == 0) ? g_x : g_hist;
    const __half* Wh = (LAYER == 0) ? g_w0h : g_w1h;
    const __half* Wl = (LAYER == 0) ? g_w0l : g_w1l;
    float* outp = (LAYER == 0) ? g_inp0 : g_inp1;

    // loader mapping
    const int ar = tid >> 1, ahalf = tid & 1;     // A: 128 rows, 2 thr/row, 32B each
    const int br = tid >> 2, bq = tid & 3;        // B: 64 rows, 4 thr/row, 16B each half
    const __half* gA  = A  + (size_t)(m0 + ar) * KD + ahalf * 16;
    const __half* gWh = Wh + (size_t)(n0 + br) * KD + bq * 8;
    const __half* gWl = Wl + (size_t)(n0 + br) * KD + bq * 8;
    const uint32_t dA  = smb + (uint32_t)ar * 80 + ahalf * 32;
    const uint32_t dBh = smb + 10240 + (uint32_t)br * 80 + bq * 16;

    float acc[2][4][4];
#pragma unroll
    for (int a = 0; a < 2; a++)
#pragma unroll
        for (int b = 0; b < 4; b++)
#pragma unroll
            for (int c = 0; c < 4; c++) acc[a][b][c] = 0.f;

    const uint32_t aFragOff = (uint32_t)(wm + (l & 15)) * 80 + (l >> 4) * 16;
    const int nloc = wn + (l & 7) + ((l >> 4) << 3);
    const uint32_t bFragOff = (uint32_t)nloc * 80 + ((l >> 3) & 1) * 16;

#define GM_STAGE(kc, s) do { \
        uint32_t o = (uint32_t)(s) * GM_BUF; \
        cp16(dA + o, gA + (kc) * 32);           cp16(dA + o + 16, gA + (kc) * 32 + 8); \
        cp16(dBh + o, gWh + (kc) * 32);         cp16(dBh + o + 5120, gWl + (kc) * 32); \
        CP_COMMIT(); \
    } while (0)

    GM_STAGE(0, 0);
    GM_STAGE(1, 1);

    for (int kc = 0; kc < NC; ++kc) {
        if (kc < NC - 1) { CP_WAIT(1); } else { CP_WAIT(0); }
        __syncthreads();
        if (kc + 2 < NC) GM_STAGE(kc + 2, (kc + 2) % 3);
        const uint32_t base = smb + (uint32_t)(kc % 3) * GM_BUF;
#pragma unroll
        for (int kk = 0; kk < 2; ++kk) {
            uint32_t a[2][4];
#pragma unroll
            for (int mc = 0; mc < 2; ++mc)
                ldsm4(a[mc], base + aFragOff + mc * 1280 + kk * 32);
            uint32_t bh[2][4];
#pragma unroll
            for (int nc = 0; nc < 2; ++nc)
                ldsm4(bh[nc], base + 10240 + bFragOff + nc * 1280 + kk * 32);
#pragma unroll
            for (int mc = 0; mc < 2; ++mc)
#pragma unroll
                for (int nc = 0; nc < 2; ++nc) {
                    mma16816(acc[mc][nc * 2 + 0], a[mc], bh[nc][0], bh[nc][1]);
                    mma16816(acc[mc][nc * 2 + 1], a[mc], bh[nc][2], bh[nc][3]);
                }
            uint32_t bl[2][4];
#pragma unroll
            for (int nc = 0; nc < 2; ++nc)
                ldsm4(bl[nc], base + 15360 + bFragOff + nc * 1280 + kk * 32);
#pragma unroll
            for (int mc = 0; mc < 2; ++mc)
#pragma unroll
                for (int nc = 0; nc < 2; ++nc) {
                    mma16816(acc[mc][nc * 2 + 0], a[mc], bl[nc][0], bl[nc][1]);
                    mma16816(acc[mc][nc * 2 + 1], a[mc], bl[nc][2], bl[nc][3]);
                }
        }
    }

    // epilogue
#pragma unroll
    for (int mc = 0; mc < 2; ++mc) {
        int r0 = m0 + wm + mc * 16 + (l >> 2);
#pragma unroll
        for (int f = 0; f < 4; ++f) {
            int c = n0 + wn + f * 8 + (l & 3) * 2;
            float bs0 = bia[c] + bib[c];
            float bs1 = bia[c + 1] + bib[c + 1];
            float2 v0 = make_float2(acc[mc][f][0] + bs0, acc[mc][f][1] + bs1);
            float2 v1 = make_float2(acc[mc][f][2] + bs0, acc[mc][f][3] + bs1);
            *(float2*)&outp[(size_t)r0 * HH + c] = v0;
            *(float2*)&outp[(size_t)(r0 + 8) * HH + c] = v1;
        }
    }
#undef GM_STAGE
}

// ----------------- persistent HMMA recurrent kernel ---------------------------------
// h_t = tanh(inp[t] + h_{t-1} @ W^T). 128 CTAs = 4 mt(64) x 32 nt(32).
// W slice [32n][1024k] fp16 hi/lo persistent in smem (stride 2064B).
// A = h (single fp16) staged in 8 chunks of K=64 per warp-group K-half,
// triple-buffered cp.async, 1 syncthreads per chunk.
// 8 warps = 2 K-groups x (2m x 2n), warp tile 32m x 16n. Partial-K reduce via smem.
#define RN_WHI 0
#define RN_WLO 66048
#define RN_A   132096
#define RN_ABUF 9216                     /* one chunk buffer: 64 rows x 144B */
#define RN_SMEM (RN_A + 6 * RN_ABUF)     /* 187392 */

template <int LAYER>
__global__ void __launch_bounds__(256, 1) rnn_tc(const float* __restrict__ W)
{
    extern __shared__ char sm[];
    const uint32_t smb = smem_u32(sm);
    const int tid = threadIdx.x, wid = tid >> 5, l = tid & 31;
    const int g = wid >> 2;            // K-group: 0 -> k[0,512), 1 -> k[512,1024)
    const int w4 = wid & 3;
    const int mt = blockIdx.x >> 5;    // 0..3
    const int nt = blockIdx.x & 31;    // 0..31
    const int m0 = mt * 64, n0 = nt * 32;
    const int wm = (w4 >> 1) * 32, wn = (w4 & 1) * 16;

    // --- W preload: fp32 -> fp16 hi/lo into padded smem [n][k], stride 2064B ---
    for (int i = tid; i < 8192; i += 256) {
        int e = i * 4;
        int n = e >> 10;
        int k = e & 1023;
        float4 w4v = *(const float4*)&W[(size_t)(n0 + n) * HH + k];
        uint32_t h0, l0, h1, l1;
        split2h(w4v.x, w4v.y, h0, l0);
        split2h(w4v.z, w4v.w, h1, l1);
        uint32_t off = (uint32_t)n * 2064 + (uint32_t)k * 2;
        *(uint2*)(sm + RN_WHI + off) = make_uint2(h0, h1);
        *(uint2*)(sm + RN_WLO + off) = make_uint2(l0, l1);
    }
    __syncthreads();

    // fragment addresses
    const uint32_t aFragOff = (uint32_t)(wm + (l & 15)) * 144 + (uint32_t)(l >> 4) * 16;
    const int nloc = wn + (l & 7) + ((l >> 4) << 3);
    const uint32_t bOffH = smb + RN_WHI + (uint32_t)nloc * 2064 + ((l >> 3) & 1) * 16;
    const uint32_t bOffL = bOffH + (RN_WLO - RN_WHI);

    // A staging: per group, 128 threads cover 64 rows x 128B (64B/thread)
    const int gt = tid & 127;
    const int sr = gt >> 1, sq = gt & 1;
    const uint32_t sdstBase = smb + RN_A + (uint32_t)g * 3 * RN_ABUF
                            + (uint32_t)sr * 144 + (uint32_t)sq * 64;

    const float* inp = (LAYER == 0) ? g_inp0 : g_inp1;
    const uint32_t psBase = smb + RN_A;   // partials: [2][64][32] fp32 (reuses A bufs)

    // epilogue thread mapping: 8 outputs per thread
    const int erow = tid >> 2;
    const int ecq  = (tid & 3) * 8;

    for (int t = 0; t < TT; ++t) {
        if (t > 0) {
            const __half* hsrc = (LAYER == 0)
                ? (g_hist + (size_t)(t - 1) * BH)
                : g_h[1 - (t & 1)];
            const __half* gsrc = hsrc + (size_t)(m0 + sr) * HH + g * 512 + sq * 32;

#define RN_STAGE(c, j) do { \
                const __half* p = gsrc + (c) * 64; \
                uint32_t d = sdstBase + (uint32_t)(j) * RN_ABUF; \
                cp16(d, p); cp16(d + 16, p + 8); \
                cp16(d + 32, p + 16); cp16(d + 48, p + 24); \
                CP_COMMIT(); \
            } while (0)

            RN_STAGE(0, 0);
            RN_STAGE(1, 1);

            float acc[2][2][4];
#pragma unroll
            for (int a = 0; a < 2; a++)
#pragma unroll
                for (int b = 0; b < 2; b++)
#pragma unroll
                    for (int c = 0; c < 4; c++) acc[a][b][c] = 0.f;

            for (int c = 0; c < 8; ++c) {
                if (c < 7) { CP_WAIT(1); } else { CP_WAIT(0); }
                __syncthreads();
                if (c + 2 < 8) RN_STAGE(c + 2, (c + 2) % 3);
                const uint32_t abase = smb + RN_A
                    + (uint32_t)(g * 3 + (c % 3)) * RN_ABUF;
#pragma unroll
                for (int kk = 0; kk < 4; ++kk) {
                    const uint32_t kb = (uint32_t)(g * 512 + c * 64 + kk * 16) * 2;
                    uint32_t a0[4], a1[4], bh[4], bl[4];
                    ldsm4(a0, abase + aFragOff + kk * 32);
                    ldsm4(a1, abase + aFragOff + 2304 + kk * 32);
                    ldsm4(bh, bOffH + kb);
                    ldsm4(bl, bOffL + kb);
                    mma16816(acc[0][0], a0, bh[0], bh[1]);
                    mma16816(acc[0][1], a0, bh[2], bh[3]);
                    mma16816(acc[1][0], a1, bh[0], bh[1]);
                    mma16816(acc[1][1], a1, bh[2], bh[3]);
                    mma16816(acc[0][0], a0, bl[0], bl[1]);
                    mma16816(acc[0][1], a0, bl[2], bl[3]);
                    mma16816(acc[1][0], a1, bl[0], bl[1]);
                    mma16816(acc[1][1], a1, bl[2], bl[3]);
                }
            }
#undef RN_STAGE

            __syncthreads();   // A bufs free; write partials
#pragma unroll
            for (int mc = 0; mc < 2; ++mc)
#pragma unroll
                for (int n8 = 0; n8 < 2; ++n8) {
                    int r = wm + mc * 16 + (l >> 2);
                    int cc = wn + n8 * 8 + (l & 3) * 2;
                    uint32_t pa = psBase + (uint32_t)g * 8192 + (uint32_t)r * 128 + cc * 4;
                    asm volatile("st.shared.v2.f32 [%0], {%1, %2};"
                                 :: "r"(pa), "f"(acc[mc][n8][0]), "f"(acc[mc][n8][1]));
                    asm volatile("st.shared.v2.f32 [%0], {%1, %2};"
                                 :: "r"(pa + 8 * 128), "f"(acc[mc][n8][2]), "f"(acc[mc][n8][3]));
                }
            __syncthreads();
        }

        // --- epilogue: v = tanh(ps0 + ps1 + inp[t]); write fp16 state ---
        {
            const float* ip = inp + (size_t)t * BH + (size_t)(m0 + erow) * HH + n0 + ecq;
            float4 i0 = *(const float4*)(ip);
            float4 i1 = *(const float4*)(ip + 4);
            float v[8] = { i0.x, i0.y, i0.z, i0.w, i1.x, i1.y, i1.z, i1.w };
            if (t > 0) {
                const uint32_t pa = psBase + (uint32_t)erow * 128 + ecq * 4;
                float4 q00, q01, q10, q11;
                asm volatile("ld.shared.v4.f32 {%0,%1,%2,%3}, [%4];"
                             : "=f"(q00.x), "=f"(q00.y), "=f"(q00.z), "=f"(q00.w) : "r"(pa));
                asm volatile("ld.shared.v4.f32 {%0,%1,%2,%3}, [%4];"
                             : "=f"(q01.x), "=f"(q01.y), "=f"(q01.z), "=f"(q01.w) : "r"(pa + 16));
                asm volatile("ld.shared.v4.f32 {%0,%1,%2,%3}, [%4];"
                             : "=f"(q10.x), "=f"(q10.y), "=f"(q10.z), "=f"(q10.w) : "r"(pa + 8192));
                asm volatile("ld.shared.v4.f32 {%0,%1,%2,%3}, [%4];"
                             : "=f"(q11.x), "=f"(q11.y), "=f"(q11.z), "=f"(q11.w) : "r"(pa + 8192 + 16));
                v[0] += q00.x + q10.x; v[1] += q00.y + q10.y;
                v[2] += q00.z + q10.z; v[3] += q00.w + q10.w;
                v[4] += q01.x + q11.x; v[5] += q01.y + q11.y;
                v[6] += q01.z + q11.z; v[7] += q01.w + q11.w;
            }
#pragma unroll
            for (int j = 0; j < 8; j++) v[j] = tanhf(v[j]);
            uint4 u;
            u.x = pack_h2(v[0], v[1]); u.y = pack_h2(v[2], v[3]);
            u.z = pack_h2(v[4], v[5]); u.w = pack_h2(v[6], v[7]);
            const size_t oidx = (size_t)(m0 + erow) * HH + n0 + ecq;
            if (LAYER == 0) {
                *(uint4*)&g_hist[(size_t)t * BH + oidx] = u;
            } else {
                *(uint4*)&g_h[t & 1][oidx] = u;
            }
        }

        grid_barrier();
    }
}

// ----------------- final FC + ReLU ---------------------------------------------------
__global__ void __launch_bounds__(256) fc_kernel(
    const float* __restrict__ fcW, const float* __restrict__ fcb,
    float* __restrict__ out)
{
    const int b = blockIdx.x;
    const int tid = threadIdx.x;
    // final h: t=255 -> buffer 1
    const __half* h = &g_h[1][(size_t)b * HH];
    float s = 0.f;
    for (int i = tid; i < HH; i += 256) s += __half2float(h[i]) * fcW[i];
#pragma unroll
    for (int o = 16; o; o >>= 1) s += __shfl_xor_sync(0xFFFFFFFFu, s, o);
    __shared__ float red[8];
    if ((tid & 31) == 0) red[tid >> 5] = s;
    __syncthreads();
    if (tid == 0) {
        float tot = 0.f;
#pragma unroll
        for (int i = 0; i < 8; i++) tot += red[i];
        out[b] = fmaxf(tot + fcb[0], 0.f);
    }
}

// ----------------- launch ------------------------------------------------------------
extern "C" void kernel_launch(void* const* d_in, const int* in_sizes, int n_in,
                              void* d_out, int out_size)
{
    const float* x     = (const float*)d_in[0];
    const float* W_ih0 = (const float*)d_in[1];
    const float* W_hh0 = (const float*)d_in[2];
    const float* b_ih0 = (const float*)d_in[3];
    const float* b_hh0 = (const float*)d_in[4];
    const float* W_ih1 = (const float*)d_in[5];
    const float* W_hh1 = (const float*)d_in[6];
    const float* b_ih1 = (const float*)d_in[7];
    const float* b_hh1 = (const float*)d_in[8];
    const float* fc_W  = (const float*)d_in[9];
    const float* fc_b  = (const float*)d_in[10];
    float* out = (float*)d_out;

    cudaFuncSetAttribute(gemm_f16<0>, cudaFuncAttributeMaxDynamicSharedMemorySize, GM_SMEM);
    cudaFuncSetAttribute(gemm_f16<1>, cudaFuncAttributeMaxDynamicSharedMemorySize, GM_SMEM);
    cudaFuncSetAttribute(rnn_tc<0>, cudaFuncAttributeMaxDynamicSharedMemorySize, RN_SMEM);
    cudaFuncSetAttribute(rnn_tc<1>, cudaFuncAttributeMaxDynamicSharedMemorySize, RN_SMEM);

    // conversions
    conv_x<<<(TT * BB * II / 4) / 256, 256>>>(x);
    conv_w<0><<<(HH * II / 4 + 255) / 256, 256>>>(W_ih0, HH * II / 4);
    conv_w<1><<<(HH * HH / 4 + 255) / 256, 256>>>(W_ih1, HH * HH / 4);

    dim3 ggrid(HH / 64, (TT * BB) / 128);  // (16, 512)
    gemm_f16<0><<<ggrid, 256, GM_SMEM>>>(b_ih0, b_hh0);
    rnn_tc<0><<<128, 256, RN_SMEM>>>(W_hh0);
    gemm_f16<1><<<ggrid, 256, GM_SMEM>>>(b_ih1, b_hh1);
    rnn_tc<1><<<128, 256, RN_SMEM>>>(W_hh1);
    fc_kernel<<<BB, 256>>>(fc_W, fc_b, out);
}

// round 6
// speedup vs baseline: 10.5272x; 1.0126x over previous
#include <cuda_runtime.h>
#include <cuda_fp16.h>
#include <math.h>
#include <stdint.h>

#define TT 256
#define BB 256
#define II 256
#define HH 1024
#define BH (BB * HH)

// ----------------- scratch (device globals; no runtime allocation) -----------------
__device__ float  g_inp0[(size_t)TT * BB * HH];      // layer0 preact [T][B][H] fp32
__device__ float  g_inp1[(size_t)TT * BB * HH];      // layer1 preact [T][B][H] fp32
__device__ __half g_x[(size_t)TT * BB * II];         // x transposed [(t*B+b)][i] fp16
__device__ __half g_hist[(size_t)TT * BB * HH];      // layer0 h history fp16
__device__ __half g_w0h[HH * II];                    // W_ih0 hi fp16
__device__ __half g_w0l[HH * II];                    // W_ih0 lo fp16
__device__ __half g_w1h[(size_t)HH * HH];            // W_ih1 hi
__device__ __half g_w1l[(size_t)HH * HH];            // W_ih1 lo
__device__ __half g_h[2][BH];                        // layer1 h ping-pong fp16
__device__ unsigned g_arrive = 0;

// ----------------- grid barrier (128 CTAs, all resident at 1 CTA/SM) ---------------
#define GBN 128u
__device__ __forceinline__ void grid_barrier() {
    __syncthreads();
    if (threadIdx.x == 0) {
        __threadfence();
        unsigned a = atomicAdd(&g_arrive, 1u) + 1u;
        unsigned target = ((a - 1u) / GBN + 1u) * GBN;
        while (*((volatile unsigned*)&g_arrive) < target) { }
        __threadfence();
    }
    __syncthreads();
}

// ----------------- portable (sm_80+) asm helpers ------------------------------------
__device__ __forceinline__ uint32_t smem_u32(const void* p) {
    uint32_t a;
    asm("{ .reg .u64 t; cvta.to.shared.u64 t, %1; cvt.u32.u64 %0, t; }" : "=r"(a) : "l"(p));
    return a;
}
__device__ __forceinline__ void cp16(uint32_t dst, const void* src) {
    asm volatile("cp.async.cg.shared.global [%0], [%1], 16;" :: "r"(dst), "l"(src));
}
#define CP_COMMIT() asm volatile("cp.async.commit_group;" ::: "memory")
#define CP_WAIT(n)  asm volatile("cp.async.wait_group %0;" :: "n"(n) : "memory")
#define BARG(id)    asm volatile("bar.sync %0, 128;" :: "r"(id) : "memory")

__device__ __forceinline__ void ldsm4(uint32_t* r, uint32_t a) {
    asm volatile("ldmatrix.sync.aligned.m8n8.x4.shared.b16 {%0,%1,%2,%3}, [%4];"
                 : "=r"(r[0]), "=r"(r[1]), "=r"(r[2]), "=r"(r[3]) : "r"(a));
}
__device__ __forceinline__ void mma16816(float* d, const uint32_t* a, uint32_t b0, uint32_t b1) {
    asm volatile(
        "mma.sync.aligned.m16n8k16.row.col.f32.f16.f16.f32 "
        "{%0,%1,%2,%3}, {%4,%5,%6,%7}, {%8,%9}, {%0,%1,%2,%3};"
        : "+f"(d[0]), "+f"(d[1]), "+f"(d[2]), "+f"(d[3])
        : "r"(a[0]), "r"(a[1]), "r"(a[2]), "r"(a[3]), "r"(b0), "r"(b1));
}

__device__ __forceinline__ uint32_t pack_h2(float a, float b) {
    __half2 h = __floats2half2_rn(a, b);
    return *(uint32_t*)&h;
}
// split two fp32 into packed fp16 hi pair + lo pair
__device__ __forceinline__ void split2h(float a, float b, uint32_t& hi, uint32_t& lo) {
    __half ah = __float2half_rn(a), bh = __float2half_rn(b);
    float ra = a - __half2float(ah), rb = b - __half2float(bh);
    hi = (uint32_t)__half_as_ushort(ah) | ((uint32_t)__half_as_ushort(bh) << 16);
    __half al = __float2half_rn(ra), bl = __float2half_rn(rb);
    lo = (uint32_t)__half_as_ushort(al) | ((uint32_t)__half_as_ushort(bl) << 16);
}

// ----------------- conversion kernels ------------------------------------------------
__global__ void __launch_bounds__(256) conv_x(const float* __restrict__ x) {
    int idx = blockIdx.x * 256 + threadIdx.x;      // one float4
    int i4  = idx & (II / 4 - 1);
    int rem = idx >> 6;                             // b*TT + t
    int t = rem & (TT - 1);
    int b = rem >> 8;
    float4 v = ((const float4*)x)[idx];
    uint32_t p0 = pack_h2(v.x, v.y);
    uint32_t p1 = pack_h2(v.z, v.w);
    *(uint2*)&g_x[((size_t)t * BB + b) * II + i4 * 4] = make_uint2(p0, p1);
}

template <int LAYER>
__global__ void __launch_bounds__(256) conv_w(const float* __restrict__ w, int n4) {
    int idx = blockIdx.x * 256 + threadIdx.x;
    if (idx >= n4) return;
    __half* dh = (LAYER == 0) ? g_w0h : g_w1h;
    __half* dl = (LAYER == 0) ? g_w0l : g_w1l;
    float4 v = ((const float4*)w)[idx];
    uint32_t h0, l0, h1, l1;
    split2h(v.x, v.y, h0, l0);
    split2h(v.z, v.w, h1, l1);
    *(uint2*)&dh[(size_t)idx * 4] = make_uint2(h0, h1);
    *(uint2*)&dl[(size_t)idx * 4] = make_uint2(l0, l1);
}

// ----------------- layer0 input GEMM (HMMA fp16, 2-term), CTA 128x64, K=256 --------
#define GM_BUF 20480
#define GM_SMEM (3 * GM_BUF)

__global__ void __launch_bounds__(256) gemm0_f16(
    const float* __restrict__ bia, const float* __restrict__ bib)
{
    constexpr int KD = II;
    constexpr int NC = KD / 32;
    extern __shared__ char sm[];
    const uint32_t smb = smem_u32(sm);
    const int tid = threadIdx.x, wid = tid >> 5, l = tid & 31;
    const int m0 = blockIdx.y * 128, n0 = blockIdx.x * 64;
    const int wm = (wid >> 1) * 32, wn = (wid & 1) * 32;

    const __half* A  = g_x;
    const __half* Wh = g_w0h;
    const __half* Wl = g_w0l;
    float* outp = g_inp0;

    const int ar = tid >> 1, ahalf = tid & 1;
    const int br = tid >> 2, bq = tid & 3;
    const __half* gA  = A  + (size_t)(m0 + ar) * KD + ahalf * 16;
    const __half* gWh = Wh + (size_t)(n0 + br) * KD + bq * 8;
    const __half* gWl = Wl + (size_t)(n0 + br) * KD + bq * 8;
    const uint32_t dA  = smb + (uint32_t)ar * 80 + ahalf * 32;
    const uint32_t dBh = smb + 10240 + (uint32_t)br * 80 + bq * 16;

    float acc[2][4][4];
#pragma unroll
    for (int a = 0; a < 2; a++)
#pragma unroll
        for (int b = 0; b < 4; b++)
#pragma unroll
            for (int c = 0; c < 4; c++) acc[a][b][c] = 0.f;

    const uint32_t aFragOff = (uint32_t)(wm + (l & 15)) * 80 + (l >> 4) * 16;
    const int nloc = wn + (l & 7) + ((l >> 4) << 3);
    const uint32_t bFragOff = (uint32_t)nloc * 80 + ((l >> 3) & 1) * 16;

#define GM_STAGE(kc, s) do { \
        uint32_t o = (uint32_t)(s) * GM_BUF; \
        cp16(dA + o, gA + (kc) * 32);           cp16(dA + o + 16, gA + (kc) * 32 + 8); \
        cp16(dBh + o, gWh + (kc) * 32);         cp16(dBh + o + 5120, gWl + (kc) * 32); \
        CP_COMMIT(); \
    } while (0)

    GM_STAGE(0, 0);
    GM_STAGE(1, 1);

    for (int kc = 0; kc < NC; ++kc) {
        if (kc < NC - 1) { CP_WAIT(1); } else { CP_WAIT(0); }
        __syncthreads();
        if (kc + 2 < NC) GM_STAGE(kc + 2, (kc + 2) % 3);
        const uint32_t base = smb + (uint32_t)(kc % 3) * GM_BUF;
#pragma unroll
        for (int kk = 0; kk < 2; ++kk) {
            uint32_t a[2][4];
#pragma unroll
            for (int mc = 0; mc < 2; ++mc)
                ldsm4(a[mc], base + aFragOff + mc * 1280 + kk * 32);
            uint32_t bh[2][4];
#pragma unroll
            for (int nc = 0; nc < 2; ++nc)
                ldsm4(bh[nc], base + 10240 + bFragOff + nc * 1280 + kk * 32);
#pragma unroll
            for (int mc = 0; mc < 2; ++mc)
#pragma unroll
                for (int nc = 0; nc < 2; ++nc) {
                    mma16816(acc[mc][nc * 2 + 0], a[mc], bh[nc][0], bh[nc][1]);
                    mma16816(acc[mc][nc * 2 + 1], a[mc], bh[nc][2], bh[nc][3]);
                }
            uint32_t bl[2][4];
#pragma unroll
            for (int nc = 0; nc < 2; ++nc)
                ldsm4(bl[nc], base + 15360 + bFragOff + nc * 1280 + kk * 32);
#pragma unroll
            for (int mc = 0; mc < 2; ++mc)
#pragma unroll
                for (int nc = 0; nc < 2; ++nc) {
                    mma16816(acc[mc][nc * 2 + 0], a[mc], bl[nc][0], bl[nc][1]);
                    mma16816(acc[mc][nc * 2 + 1], a[mc], bl[nc][2], bl[nc][3]);
                }
        }
    }

#pragma unroll
    for (int mc = 0; mc < 2; ++mc) {
        int r0 = m0 + wm + mc * 16 + (l >> 2);
#pragma unroll
        for (int f = 0; f < 4; ++f) {
            int c = n0 + wn + f * 8 + (l & 3) * 2;
            float bs0 = bia[c] + bib[c];
            float bs1 = bia[c + 1] + bib[c + 1];
            float2 v0 = make_float2(acc[mc][f][0] + bs0, acc[mc][f][1] + bs1);
            float2 v1 = make_float2(acc[mc][f][2] + bs0, acc[mc][f][3] + bs1);
            *(float2*)&outp[(size_t)r0 * HH + c] = v0;
            *(float2*)&outp[(size_t)(r0 + 8) * HH + c] = v1;
        }
    }
#undef GM_STAGE
}

// ----------------- layer1 input GEMM: CTA 128m x 128n, K=1024 ------------------------
// Halves A DRAM re-reads vs BN=64 (8 n-tiles instead of 16). 8 warps = 4m x 2n,
// warp tile 32m x 64n. 3-stage cp.async.
// stage: A 128x80=10240 | Bh 128x80=10240 | Bl 10240 -> 30720
#define G1_BUF 30720
#define G1_SMEM (3 * G1_BUF)

__global__ void __launch_bounds__(256) gemm1_f16(
    const float* __restrict__ bia, const float* __restrict__ bib)
{
    constexpr int KD = HH;
    constexpr int NC = KD / 32;   // 32
    extern __shared__ char sm[];
    const uint32_t smb = smem_u32(sm);
    const int tid = threadIdx.x, wid = tid >> 5, l = tid & 31;
    const int m0 = blockIdx.y * 128, n0 = blockIdx.x * 128;
    const int wm = (wid >> 1) * 32, wn = (wid & 1) * 64;

    const int ar = tid >> 1, ahalf = tid & 1;   // A: 128 rows, 2 thr/row, 32B
    const __half* gA  = g_hist + (size_t)(m0 + ar) * KD + ahalf * 16;
    const __half* gWh = g_w1h + (size_t)(n0 + ar) * KD + ahalf * 16;
    const __half* gWl = g_w1l + (size_t)(n0 + ar) * KD + ahalf * 16;
    const uint32_t dA  = smb + (uint32_t)ar * 80 + ahalf * 32;
    const uint32_t dBh = dA + 10240;
    const uint32_t dBl = dA + 20480;

    float acc[2][8][4];
#pragma unroll
    for (int a = 0; a < 2; a++)
#pragma unroll
        for (int b = 0; b < 8; b++)
#pragma unroll
            for (int c = 0; c < 4; c++) acc[a][b][c] = 0.f;

    const uint32_t aFragOff = (uint32_t)(wm + (l & 15)) * 80 + (l >> 4) * 16;
    const int nloc = wn + (l & 7) + ((l >> 4) << 3);
    const uint32_t bFragOff = (uint32_t)nloc * 80 + ((l >> 3) & 1) * 16;

#define G1_STAGE(kc, s) do { \
        uint32_t o = (uint32_t)(s) * G1_BUF; \
        const __half* pA = gA + (kc) * 32; \
        const __half* pH = gWh + (kc) * 32; \
        const __half* pL = gWl + (kc) * 32; \
        cp16(dA + o, pA);        cp16(dA + o + 16, pA + 8); \
        cp16(dBh + o, pH);       cp16(dBh + o + 16, pH + 8); \
        cp16(dBl + o, pL);       cp16(dBl + o + 16, pL + 8); \
        CP_COMMIT(); \
    } while (0)

    G1_STAGE(0, 0);
    G1_STAGE(1, 1);

    for (int kc = 0; kc < NC; ++kc) {
        if (kc < NC - 1) { CP_WAIT(1); } else { CP_WAIT(0); }
        __syncthreads();
        if (kc + 2 < NC) G1_STAGE(kc + 2, (kc + 2) % 3);
        const uint32_t base = smb + (uint32_t)(kc % 3) * G1_BUF;
#pragma unroll
        for (int kk = 0; kk < 2; ++kk) {
            uint32_t a[2][4];
#pragma unroll
            for (int mc = 0; mc < 2; ++mc)
                ldsm4(a[mc], base + aFragOff + mc * 1280 + kk * 32);
            uint32_t bh[4][4];
#pragma unroll
            for (int nc = 0; nc < 4; ++nc)
                ldsm4(bh[nc], base + 10240 + bFragOff + nc * 1280 + kk * 32);
#pragma unroll
            for (int mc = 0; mc < 2; ++mc)
#pragma unroll
                for (int nc = 0; nc < 4; ++nc) {
                    mma16816(acc[mc][nc * 2 + 0], a[mc], bh[nc][0], bh[nc][1]);
                    mma16816(acc[mc][nc * 2 + 1], a[mc], bh[nc][2], bh[nc][3]);
                }
            uint32_t bl[4][4];
#pragma unroll
            for (int nc = 0; nc < 4; ++nc)
                ldsm4(bl[nc], base + 20480 + bFragOff + nc * 1280 + kk * 32);
#pragma unroll
            for (int mc = 0; mc < 2; ++mc)
#pragma unroll
                for (int nc = 0; nc < 4; ++nc) {
                    mma16816(acc[mc][nc * 2 + 0], a[mc], bl[nc][0], bl[nc][1]);
                    mma16816(acc[mc][nc * 2 + 1], a[mc], bl[nc][2], bl[nc][3]);
                }
        }
    }

#pragma unroll
    for (int mc = 0; mc < 2; ++mc) {
        int r0 = m0 + wm + mc * 16 + (l >> 2);
#pragma unroll
        for (int f = 0; f < 8; ++f) {
            int c = n0 + wn + f * 8 + (l & 3) * 2;
            float bs0 = bia[c] + bib[c];
            float bs1 = bia[c + 1] + bib[c + 1];
            float2 v0 = make_float2(acc[mc][f][0] + bs0, acc[mc][f][1] + bs1);
            float2 v1 = make_float2(acc[mc][f][2] + bs0, acc[mc][f][3] + bs1);
            *(float2*)&g_inp1[(size_t)r0 * HH + c] = v0;
            *(float2*)&g_inp1[(size_t)(r0 + 8) * HH + c] = v1;
        }
    }
#undef G1_STAGE
}

// ----------------- persistent HMMA recurrent kernel ---------------------------------
// h_t = tanh(inp[t] + h_{t-1} @ W^T). 128 CTAs = 4 mt(64) x 32 nt(32).
// W slice [32n][1024k] fp16 hi/lo persistent in smem (stride 2064B).
// A (fp16) staged in 8 chunks of K=64 per K-group, 3-buffer cp.async.
// Group g's stagers == group g's consumer warps -> named barrier (1+g, 128 threads)
// replaces per-chunk __syncthreads. inp[t] prefetched to regs at step start.
#define RN_WHI 0
#define RN_WLO 66048
#define RN_A   132096
#define RN_ABUF 9216                     /* one chunk buffer: 64 rows x 144B */
#define RN_SMEM (RN_A + 6 * RN_ABUF)     /* 187392 */

template <int LAYER>
__global__ void __launch_bounds__(256, 1) rnn_tc(const float* __restrict__ W)
{
    extern __shared__ char sm[];
    const uint32_t smb = smem_u32(sm);
    const int tid = threadIdx.x, wid = tid >> 5, l = tid & 31;
    const int g = wid >> 2;            // K-group: 0 -> k[0,512), 1 -> k[512,1024)
    const int w4 = wid & 3;
    const int mt = blockIdx.x >> 5;    // 0..3
    const int nt = blockIdx.x & 31;    // 0..31
    const int m0 = mt * 64, n0 = nt * 32;
    const int wm = (w4 >> 1) * 32, wn = (w4 & 1) * 16;

    // --- W preload: fp32 -> fp16 hi/lo into padded smem [n][k], stride 2064B ---
    for (int i = tid; i < 8192; i += 256) {
        int e = i * 4;
        int n = e >> 10;
        int k = e & 1023;
        float4 w4v = *(const float4*)&W[(size_t)(n0 + n) * HH + k];
        uint32_t h0, l0, h1, l1;
        split2h(w4v.x, w4v.y, h0, l0);
        split2h(w4v.z, w4v.w, h1, l1);
        uint32_t off = (uint32_t)n * 2064 + (uint32_t)k * 2;
        *(uint2*)(sm + RN_WHI + off) = make_uint2(h0, h1);
        *(uint2*)(sm + RN_WLO + off) = make_uint2(l0, l1);
    }
    __syncthreads();

    const uint32_t aFragOff = (uint32_t)(wm + (l & 15)) * 144 + (uint32_t)(l >> 4) * 16;
    const int nloc = wn + (l & 7) + ((l >> 4) << 3);
    const uint32_t bOffH = smb + RN_WHI + (uint32_t)nloc * 2064 + ((l >> 3) & 1) * 16;
    const uint32_t bOffL = bOffH + (RN_WLO - RN_WHI);

    // A staging: per group, 128 threads cover 64 rows x 128B (64B/thread)
    const int gt = tid & 127;
    const int sr = gt >> 1, sq = gt & 1;
    const uint32_t sdstBase = smb + RN_A + (uint32_t)g * 3 * RN_ABUF
                            + (uint32_t)sr * 144 + (uint32_t)sq * 64;
    const int gbar = 1 + g;

    const float* inp = (LAYER == 0) ? g_inp0 : g_inp1;
    const uint32_t psBase = smb + RN_A;   // partials: [2][64][32] fp32 (reuses A bufs)

    // epilogue thread mapping: 8 outputs per thread
    const int erow = tid >> 2;
    const int ecq  = (tid & 3) * 8;

    for (int t = 0; t < TT; ++t) {
        // prefetch inp[t] early; latency overlaps the MMA phase
        const float* ip = inp + (size_t)t * BH + (size_t)(m0 + erow) * HH + n0 + ecq;
        float4 pi0 = __ldg((const float4*)ip);
        float4 pi1 = __ldg((const float4*)(ip + 4));

        if (t > 0) {
            const __half* hsrc = (LAYER == 0)
                ? (g_hist + (size_t)(t - 1) * BH)
                : g_h[1 - (t & 1)];
            const __half* gsrc = hsrc + (size_t)(m0 + sr) * HH + g * 512 + sq * 32;

#define RN_STAGE(c, j) do { \
                const __half* p = gsrc + (c) * 64; \
                uint32_t d = sdstBase + (uint32_t)(j) * RN_ABUF; \
                cp16(d, p); cp16(d + 16, p + 8); \
                cp16(d + 32, p + 16); cp16(d + 48, p + 24); \
                CP_COMMIT(); \
            } while (0)

            RN_STAGE(0, 0);
            RN_STAGE(1, 1);

            float acc[2][2][4];
#pragma unroll
            for (int a = 0; a < 2; a++)
#pragma unroll
                for (int b = 0; b < 2; b++)
#pragma unroll
                    for (int c = 0; c < 4; c++) acc[a][b][c] = 0.f;

            for (int c = 0; c < 8; ++c) {
                if (c < 7) { CP_WAIT(1); } else { CP_WAIT(0); }
                BARG(gbar);
                if (c + 2 < 8) RN_STAGE(c + 2, (c + 2) % 3);
                const uint32_t abase = smb + RN_A
                    + (uint32_t)(g * 3 + (c % 3)) * RN_ABUF;
#pragma unroll
                for (int kk = 0; kk < 4; ++kk) {
                    const uint32_t kb = (uint32_t)(g * 512 + c * 64 + kk * 16) * 2;
                    uint32_t a0[4], a1[4], bh[4], bl[4];
                    ldsm4(a0, abase + aFragOff + kk * 32);
                    ldsm4(a1, abase + aFragOff + 2304 + kk * 32);
                    ldsm4(bh, bOffH + kb);
                    ldsm4(bl, bOffL + kb);
                    mma16816(acc[0][0], a0, bh[0], bh[1]);
                    mma16816(acc[0][1], a0, bh[2], bh[3]);
                    mma16816(acc[1][0], a1, bh[0], bh[1]);
                    mma16816(acc[1][1], a1, bh[2], bh[3]);
                    mma16816(acc[0][0], a0, bl[0], bl[1]);
                    mma16816(acc[0][1], a0, bl[2], bl[3]);
                    mma16816(acc[1][0], a1, bl[0], bl[1]);
                    mma16816(acc[1][1], a1, bl[2], bl[3]);
                }
            }
#undef RN_STAGE

            __syncthreads();   // both groups done; A bufs free -> write partials
#pragma unroll
            for (int mc = 0; mc < 2; ++mc)
#pragma unroll
                for (int n8 = 0; n8 < 2; ++n8) {
                    int r = wm + mc * 16 + (l >> 2);
                    int cc = wn + n8 * 8 + (l & 3) * 2;
                    uint32_t pa = psBase + (uint32_t)g * 8192 + (uint32_t)r * 128 + cc * 4;
                    asm volatile("st.shared.v2.f32 [%0], {%1, %2};"
                                 :: "r"(pa), "f"(acc[mc][n8][0]), "f"(acc[mc][n8][1]));
                    asm volatile("st.shared.v2.f32 [%0], {%1, %2};"
                                 :: "r"(pa + 8 * 128), "f"(acc[mc][n8][2]), "f"(acc[mc][n8][3]));
                }
            __syncthreads();
        }

        // --- epilogue: v = tanh(ps0 + ps1 + inp[t]); write fp16 state ---
        {
            float v[8] = { pi0.x, pi0.y, pi0.z, pi0.w, pi1.x, pi1.y, pi1.z, pi1.w };
            if (t > 0) {
                const uint32_t pa = psBase + (uint32_t)erow * 128 + ecq * 4;
                float4 q00, q01, q10, q11;
                asm volatile("ld.shared.v4.f32 {%0,%1,%2,%3}, [%4];"
                             : "=f"(q00.x), "=f"(q00.y), "=f"(q00.z), "=f"(q00.w) : "r"(pa));
                asm volatile("ld.shared.v4.f32 {%0,%1,%2,%3}, [%4];"
                             : "=f"(q01.x), "=f"(q01.y), "=f"(q01.z), "=f"(q01.w) : "r"(pa + 16));
                asm volatile("ld.shared.v4.f32 {%0,%1,%2,%3}, [%4];"
                             : "=f"(q10.x), "=f"(q10.y), "=f"(q10.z), "=f"(q10.w) : "r"(pa + 8192));
                asm volatile("ld.shared.v4.f32 {%0,%1,%2,%3}, [%4];"
                             : "=f"(q11.x), "=f"(q11.y), "=f"(q11.z), "=f"(q11.w) : "r"(pa + 8192 + 16));
                v[0] += q00.x + q10.x; v[1] += q00.y + q10.y;
                v[2] += q00.z + q10.z; v[3] += q00.w + q10.w;
                v[4] += q01.x + q11.x; v[5] += q01.y + q11.y;
                v[6] += q01.z + q11.z; v[7] += q01.w + q11.w;
            }
#pragma unroll
            for (int j = 0; j < 8; j++) v[j] = tanhf(v[j]);
            uint4 u;
            u.x = pack_h2(v[0], v[1]); u.y = pack_h2(v[2], v[3]);
            u.z = pack_h2(v[4], v[5]); u.w = pack_h2(v[6], v[7]);
            const size_t oidx = (size_t)(m0 + erow) * HH + n0 + ecq;
            if (LAYER == 0) {
                *(uint4*)&g_hist[(size_t)t * BH + oidx] = u;
            } else {
                *(uint4*)&g_h[t & 1][oidx] = u;
            }
        }

        grid_barrier();
    }
}

// ----------------- final FC + ReLU ---------------------------------------------------
__global__ void __launch_bounds__(256) fc_kernel(
    const float* __restrict__ fcW, const float* __restrict__ fcb,
    float* __restrict__ out)
{
    const int b = blockIdx.x;
    const int tid = threadIdx.x;
    const __half* h = &g_h[1][(size_t)b * HH];   // t=255 -> buffer 1
    float s = 0.f;
    for (int i = tid; i < HH; i += 256) s += __half2float(h[i]) * fcW[i];
#pragma unroll
    for (int o = 16; o; o >>= 1) s += __shfl_xor_sync(0xFFFFFFFFu, s, o);
    __shared__ float red[8];
    if ((tid & 31) == 0) red[tid >> 5] = s;
    __syncthreads();
    if (tid == 0) {
        float tot = 0.f;
#pragma unroll
        for (int i = 0; i < 8; i++) tot += red[i];
        out[b] = fmaxf(tot + fcb[0], 0.f);
    }
}

// ----------------- launch ------------------------------------------------------------
extern "C" void kernel_launch(void* const* d_in, const int* in_sizes, int n_in,
                              void* d_out, int out_size)
{
    const float* x     = (const float*)d_in[0];
    const float* W_ih0 = (const float*)d_in[1];
    const float* W_hh0 = (const float*)d_in[2];
    const float* b_ih0 = (const float*)d_in[3];
    const float* b_hh0 = (const float*)d_in[4];
    const float* W_ih1 = (const float*)d_in[5];
    const float* W_hh1 = (const float*)d_in[6];
    const float* b_ih1 = (const float*)d_in[7];
    const float* b_hh1 = (const float*)d_in[8];
    const float* fc_W  = (const float*)d_in[9];
    const float* fc_b  = (const float*)d_in[10];
    float* out = (float*)d_out;

    cudaFuncSetAttribute(gemm0_f16, cudaFuncAttributeMaxDynamicSharedMemorySize, GM_SMEM);
    cudaFuncSetAttribute(gemm1_f16, cudaFuncAttributeMaxDynamicSharedMemorySize, G1_SMEM);
    cudaFuncSetAttribute(rnn_tc<0>, cudaFuncAttributeMaxDynamicSharedMemorySize, RN_SMEM);
    cudaFuncSetAttribute(rnn_tc<1>, cudaFuncAttributeMaxDynamicSharedMemorySize, RN_SMEM);

    // conversions
    conv_x<<<(TT * BB * II / 4) / 256, 256>>>(x);
    conv_w<0><<<(HH * II / 4 + 255) / 256, 256>>>(W_ih0, HH * II / 4);
    conv_w<1><<<(HH * HH / 4 + 255) / 256, 256>>>(W_ih1, HH * HH / 4);

    dim3 g0grid(HH / 64, (TT * BB) / 128);   // (16, 512)
    gemm0_f16<<<g0grid, 256, GM_SMEM>>>(b_ih0, b_hh0);
    rnn_tc<0><<<128, 256, RN_SMEM>>>(W_hh0);
    dim3 g1grid(HH / 128, (TT * BB) / 128);  // (8, 512)
    gemm1_f16<<<g1grid, 256, G1_SMEM>>>(b_ih1, b_hh1);
    rnn_tc<1><<<128, 256, RN_SMEM>>>(W_hh1);
    fc_kernel<<<BB, 256>>>(fc_W, fc_b, out);
}

// round 7
// speedup vs baseline: 10.9238x; 1.0377x over previous
#include <cuda_runtime.h>
#include <cuda_fp16.h>
#include <math.h>
#include <stdint.h>

#define TT 256
#define BB 256
#define II 256
#define HH 1024
#define BH (BB * HH)

// ----------------- scratch (device globals; no runtime allocation) -----------------
__device__ __half g_inp0[(size_t)TT * BB * HH];      // layer0 preact [T][B][H] fp16
__device__ __half g_inp1[(size_t)TT * BB * HH];      // layer1 preact [T][B][H] fp16
__device__ __half g_x[(size_t)TT * BB * II];         // x transposed [(t*B+b)][i] fp16
__device__ __half g_hist[(size_t)TT * BB * HH];      // layer0 h history fp16
__device__ __half g_w0h[HH * II];                    // W_ih0 hi fp16
__device__ __half g_w0l[HH * II];                    // W_ih0 lo fp16
__device__ __half g_w1h[(size_t)HH * HH];            // W_ih1 hi
__device__ __half g_w1l[(size_t)HH * HH];            // W_ih1 lo
__device__ __half g_h[2][BH];                        // layer1 h ping-pong fp16
__device__ unsigned g_arr[4 * 64];                   // per-mt-group barrier counters (256B apart)

// ----------------- mt-group barrier (32 CTAs per group) -----------------------------
__device__ __forceinline__ void group_barrier(int mt) {
    __syncthreads();
    if (threadIdx.x == 0) {
        __threadfence();
        unsigned* ctr = &g_arr[mt * 64];
        unsigned a = atomicAdd(ctr, 1u) + 1u;
        unsigned target = ((a - 1u) / 32u + 1u) * 32u;
        while (*((volatile unsigned*)ctr) < target) { }
        __threadfence();
    }
    __syncthreads();
}

// ----------------- portable (sm_80+) asm helpers ------------------------------------
__device__ __forceinline__ uint32_t smem_u32(const void* p) {
    uint32_t a;
    asm("{ .reg .u64 t; cvta.to.shared.u64 t, %1; cvt.u32.u64 %0, t; }" : "=r"(a) : "l"(p));
    return a;
}
__device__ __forceinline__ void cp16(uint32_t dst, const void* src) {
    asm volatile("cp.async.cg.shared.global [%0], [%1], 16;" :: "r"(dst), "l"(src));
}
#define CP_COMMIT() asm volatile("cp.async.commit_group;" ::: "memory")
#define CP_WAIT(n)  asm volatile("cp.async.wait_group %0;" :: "n"(n) : "memory")
#define BARG(id)    asm volatile("bar.sync %0, 128;" :: "r"(id) : "memory")

__device__ __forceinline__ void ldsm4(uint32_t* r, uint32_t a) {
    asm volatile("ldmatrix.sync.aligned.m8n8.x4.shared.b16 {%0,%1,%2,%3}, [%4];"
                 : "=r"(r[0]), "=r"(r[1]), "=r"(r[2]), "=r"(r[3]) : "r"(a));
}
__device__ __forceinline__ void mma16816(float* d, const uint32_t* a, uint32_t b0, uint32_t b1) {
    asm volatile(
        "mma.sync.aligned.m16n8k16.row.col.f32.f16.f16.f32 "
        "{%0,%1,%2,%3}, {%4,%5,%6,%7}, {%8,%9}, {%0,%1,%2,%3};"
        : "+f"(d[0]), "+f"(d[1]), "+f"(d[2]), "+f"(d[3])
        : "r"(a[0]), "r"(a[1]), "r"(a[2]), "r"(a[3]), "r"(b0), "r"(b1));
}

__device__ __forceinline__ uint32_t pack_h2(float a, float b) {
    __half2 h = __floats2half2_rn(a, b);
    return *(uint32_t*)&h;
}
__device__ __forceinline__ void split2h(float a, float b, uint32_t& hi, uint32_t& lo) {
    __half ah = __float2half_rn(a), bh = __float2half_rn(b);
    float ra = a - __half2float(ah), rb = b - __half2float(bh);
    hi = (uint32_t)__half_as_ushort(ah) | ((uint32_t)__half_as_ushort(bh) << 16);
    __half al = __float2half_rn(ra), bl = __float2half_rn(rb);
    lo = (uint32_t)__half_as_ushort(al) | ((uint32_t)__half_as_ushort(bl) << 16);
}

// ----------------- conversion kernels ------------------------------------------------
__global__ void __launch_bounds__(256) conv_x(const float* __restrict__ x) {
    int idx = blockIdx.x * 256 + threadIdx.x;      // one float4
    int i4  = idx & (II / 4 - 1);
    int rem = idx >> 6;                             // b*TT + t
    int t = rem & (TT - 1);
    int b = rem >> 8;
    float4 v = ((const float4*)x)[idx];
    uint32_t p0 = pack_h2(v.x, v.y);
    uint32_t p1 = pack_h2(v.z, v.w);
    *(uint2*)&g_x[((size_t)t * BB + b) * II + i4 * 4] = make_uint2(p0, p1);
}

template <int LAYER>
__global__ void __launch_bounds__(256) conv_w(const float* __restrict__ w, int n4) {
    int idx = blockIdx.x * 256 + threadIdx.x;
    if (idx >= n4) return;
    __half* dh = (LAYER == 0) ? g_w0h : g_w1h;
    __half* dl = (LAYER == 0) ? g_w0l : g_w1l;
    float4 v = ((const float4*)w)[idx];
    uint32_t h0, l0, h1, l1;
    split2h(v.x, v.y, h0, l0);
    split2h(v.z, v.w, h1, l1);
    *(uint2*)&dh[(size_t)idx * 4] = make_uint2(h0, h1);
    *(uint2*)&dl[(size_t)idx * 4] = make_uint2(l0, l1);
}

// ----------------- layer0 input GEMM (HMMA fp16, 2-term), CTA 128x64, K=256 --------
#define GM_BUF 20480
#define GM_SMEM (3 * GM_BUF)

__global__ void __launch_bounds__(256) gemm0_f16(
    const float* __restrict__ bia, const float* __restrict__ bib)
{
    constexpr int KD = II;
    constexpr int NC = KD / 32;
    extern __shared__ char sm[];
    const uint32_t smb = smem_u32(sm);
    const int tid = threadIdx.x, wid = tid >> 5, l = tid & 31;
    const int m0 = blockIdx.y * 128, n0 = blockIdx.x * 64;
    const int wm = (wid >> 1) * 32, wn = (wid & 1) * 32;

    const int ar = tid >> 1, ahalf = tid & 1;
    const int br = tid >> 2, bq = tid & 3;
    const __half* gA  = g_x   + (size_t)(m0 + ar) * KD + ahalf * 16;
    const __half* gWh = g_w0h + (size_t)(n0 + br) * KD + bq * 8;
    const __half* gWl = g_w0l + (size_t)(n0 + br) * KD + bq * 8;
    const uint32_t dA  = smb + (uint32_t)ar * 80 + ahalf * 32;
    const uint32_t dBh = smb + 10240 + (uint32_t)br * 80 + bq * 16;

    float acc[2][4][4];
#pragma unroll
    for (int a = 0; a < 2; a++)
#pragma unroll
        for (int b = 0; b < 4; b++)
#pragma unroll
            for (int c = 0; c < 4; c++) acc[a][b][c] = 0.f;

    const uint32_t aFragOff = (uint32_t)(wm + (l & 15)) * 80 + (l >> 4) * 16;
    const int nloc = wn + (l & 7) + ((l >> 4) << 3);
    const uint32_t bFragOff = (uint32_t)nloc * 80 + ((l >> 3) & 1) * 16;

#define GM_STAGE(kc, s) do { \
        uint32_t o = (uint32_t)(s) * GM_BUF; \
        cp16(dA + o, gA + (kc) * 32);           cp16(dA + o + 16, gA + (kc) * 32 + 8); \
        cp16(dBh + o, gWh + (kc) * 32);         cp16(dBh + o + 5120, gWl + (kc) * 32); \
        CP_COMMIT(); \
    } while (0)

    GM_STAGE(0, 0);
    GM_STAGE(1, 1);

    for (int kc = 0; kc < NC; ++kc) {
        if (kc < NC - 1) { CP_WAIT(1); } else { CP_WAIT(0); }
        __syncthreads();
        if (kc + 2 < NC) GM_STAGE(kc + 2, (kc + 2) % 3);
        const uint32_t base = smb + (uint32_t)(kc % 3) * GM_BUF;
#pragma unroll
        for (int kk = 0; kk < 2; ++kk) {
            uint32_t a[2][4];
#pragma unroll
            for (int mc = 0; mc < 2; ++mc)
                ldsm4(a[mc], base + aFragOff + mc * 1280 + kk * 32);
            uint32_t bh[2][4];
#pragma unroll
            for (int nc = 0; nc < 2; ++nc)
                ldsm4(bh[nc], base + 10240 + bFragOff + nc * 1280 + kk * 32);
#pragma unroll
            for (int mc = 0; mc < 2; ++mc)
#pragma unroll
                for (int nc = 0; nc < 2; ++nc) {
                    mma16816(acc[mc][nc * 2 + 0], a[mc], bh[nc][0], bh[nc][1]);
                    mma16816(acc[mc][nc * 2 + 1], a[mc], bh[nc][2], bh[nc][3]);
                }
            uint32_t bl[2][4];
#pragma unroll
            for (int nc = 0; nc < 2; ++nc)
                ldsm4(bl[nc], base + 15360 + bFragOff + nc * 1280 + kk * 32);
#pragma unroll
            for (int mc = 0; mc < 2; ++mc)
#pragma unroll
                for (int nc = 0; nc < 2; ++nc) {
                    mma16816(acc[mc][nc * 2 + 0], a[mc], bl[nc][0], bl[nc][1]);
                    mma16816(acc[mc][nc * 2 + 1], a[mc], bl[nc][2], bl[nc][3]);
                }
        }
    }

    // epilogue: fp16 output (halves write traffic)
#pragma unroll
    for (int mc = 0; mc < 2; ++mc) {
        int r0 = m0 + wm + mc * 16 + (l >> 2);
#pragma unroll
        for (int f = 0; f < 4; ++f) {
            int c = n0 + wn + f * 8 + (l & 3) * 2;
            float bs0 = bia[c] + bib[c];
            float bs1 = bia[c + 1] + bib[c + 1];
            *(uint32_t*)&g_inp0[(size_t)r0 * HH + c] =
                pack_h2(acc[mc][f][0] + bs0, acc[mc][f][1] + bs1);
            *(uint32_t*)&g_inp0[(size_t)(r0 + 8) * HH + c] =
                pack_h2(acc[mc][f][2] + bs0, acc[mc][f][3] + bs1);
        }
    }
#undef GM_STAGE
}

// ----------------- layer1 input GEMM: CTA 128m x 128n, K=1024 ------------------------
#define G1_BUF 30720
#define G1_SMEM (3 * G1_BUF)

__global__ void __launch_bounds__(256) gemm1_f16(
    const float* __restrict__ bia, const float* __restrict__ bib)
{
    constexpr int KD = HH;
    constexpr int NC = KD / 32;   // 32
    extern __shared__ char sm[];
    const uint32_t smb = smem_u32(sm);
    const int tid = threadIdx.x, wid = tid >> 5, l = tid & 31;
    const int m0 = blockIdx.y * 128, n0 = blockIdx.x * 128;
    const int wm = (wid >> 1) * 32, wn = (wid & 1) * 64;

    const int ar = tid >> 1, ahalf = tid & 1;   // 128 rows, 2 thr/row, 32B
    const __half* gA  = g_hist + (size_t)(m0 + ar) * KD + ahalf * 16;
    const __half* gWh = g_w1h + (size_t)(n0 + ar) * KD + ahalf * 16;
    const __half* gWl = g_w1l + (size_t)(n0 + ar) * KD + ahalf * 16;
    const uint32_t dA  = smb + (uint32_t)ar * 80 + ahalf * 32;
    const uint32_t dBh = dA + 10240;
    const uint32_t dBl = dA + 20480;

    float acc[2][8][4];
#pragma unroll
    for (int a = 0; a < 2; a++)
#pragma unroll
        for (int b = 0; b < 8; b++)
#pragma unroll
            for (int c = 0; c < 4; c++) acc[a][b][c] = 0.f;

    const uint32_t aFragOff = (uint32_t)(wm + (l & 15)) * 80 + (l >> 4) * 16;
    const int nloc = wn + (l & 7) + ((l >> 4) << 3);
    const uint32_t bFragOff = (uint32_t)nloc * 80 + ((l >> 3) & 1) * 16;

#define G1_STAGE(kc, s) do { \
        uint32_t o = (uint32_t)(s) * G1_BUF; \
        const __half* pA = gA + (kc) * 32; \
        const __half* pH = gWh + (kc) * 32; \
        const __half* pL = gWl + (kc) * 32; \
        cp16(dA + o, pA);        cp16(dA + o + 16, pA + 8); \
        cp16(dBh + o, pH);       cp16(dBh + o + 16, pH + 8); \
        cp16(dBl + o, pL);       cp16(dBl + o + 16, pL + 8); \
        CP_COMMIT(); \
    } while (0)

    G1_STAGE(0, 0);
    G1_STAGE(1, 1);

    for (int kc = 0; kc < NC; ++kc) {
        if (kc < NC - 1) { CP_WAIT(1); } else { CP_WAIT(0); }
        __syncthreads();
        if (kc + 2 < NC) G1_STAGE(kc + 2, (kc + 2) % 3);
        const uint32_t base = smb + (uint32_t)(kc % 3) * G1_BUF;
#pragma unroll
        for (int kk = 0; kk < 2; ++kk) {
            uint32_t a[2][4];
#pragma unroll
            for (int mc = 0; mc < 2; ++mc)
                ldsm4(a[mc], base + aFragOff + mc * 1280 + kk * 32);
            uint32_t bh[4][4];
#pragma unroll
            for (int nc = 0; nc < 4; ++nc)
                ldsm4(bh[nc], base + 10240 + bFragOff + nc * 1280 + kk * 32);
#pragma unroll
            for (int mc = 0; mc < 2; ++mc)
#pragma unroll
                for (int nc = 0; nc < 4; ++nc) {
                    mma16816(acc[mc][nc * 2 + 0], a[mc], bh[nc][0], bh[nc][1]);
                    mma16816(acc[mc][nc * 2 + 1], a[mc], bh[nc][2], bh[nc][3]);
                }
            uint32_t bl[4][4];
#pragma unroll
            for (int nc = 0; nc < 4; ++nc)
                ldsm4(bl[nc], base + 20480 + bFragOff + nc * 1280 + kk * 32);
#pragma unroll
            for (int mc = 0; mc < 2; ++mc)
#pragma unroll
                for (int nc = 0; nc < 4; ++nc) {
                    mma16816(acc[mc][nc * 2 + 0], a[mc], bl[nc][0], bl[nc][1]);
                    mma16816(acc[mc][nc * 2 + 1], a[mc], bl[nc][2], bl[nc][3]);
                }
        }
    }

#pragma unroll
    for (int mc = 0; mc < 2; ++mc) {
        int r0 = m0 + wm + mc * 16 + (l >> 2);
#pragma unroll
        for (int f = 0; f < 8; ++f) {
            int c = n0 + wn + f * 8 + (l & 3) * 2;
            float bs0 = bia[c] + bib[c];
            float bs1 = bia[c + 1] + bib[c + 1];
            *(uint32_t*)&g_inp1[(size_t)r0 * HH + c] =
                pack_h2(acc[mc][f][0] + bs0, acc[mc][f][1] + bs1);
            *(uint32_t*)&g_inp1[(size_t)(r0 + 8) * HH + c] =
                pack_h2(acc[mc][f][2] + bs0, acc[mc][f][3] + bs1);
        }
    }
#undef G1_STAGE
}

// ----------------- persistent HMMA recurrent kernel ---------------------------------
// h_t = tanh(inp[t] + h_{t-1} @ W^T). 128 CTAs = 4 mt(64) x 32 nt(32).
// Per-step sync: mt-group barrier over 32 CTAs (CTA (mt,nt) at t+1 reads only its
// own 64 batch rows of h -> producers are exactly the same-mt CTAs).
#define RN_WHI 0
#define RN_WLO 66048
#define RN_A   132096
#define RN_ABUF 9216                     /* one chunk buffer: 64 rows x 144B */
#define RN_SMEM (RN_A + 6 * RN_ABUF)     /* 187392 */

template <int LAYER>
__global__ void __launch_bounds__(256, 1) rnn_tc(const float* __restrict__ W)
{
    extern __shared__ char sm[];
    const uint32_t smb = smem_u32(sm);
    const int tid = threadIdx.x, wid = tid >> 5, l = tid & 31;
    const int g = wid >> 2;            // K-group: 0 -> k[0,512), 1 -> k[512,1024)
    const int w4 = wid & 3;
    const int mt = blockIdx.x >> 5;    // 0..3
    const int nt = blockIdx.x & 31;    // 0..31
    const int m0 = mt * 64, n0 = nt * 32;
    const int wm = (w4 >> 1) * 32, wn = (w4 & 1) * 16;

    // --- W preload: fp32 -> fp16 hi/lo into padded smem [n][k], stride 2064B ---
    for (int i = tid; i < 8192; i += 256) {
        int e = i * 4;
        int n = e >> 10;
        int k = e & 1023;
        float4 w4v = *(const float4*)&W[(size_t)(n0 + n) * HH + k];
        uint32_t h0, l0, h1, l1;
        split2h(w4v.x, w4v.y, h0, l0);
        split2h(w4v.z, w4v.w, h1, l1);
        uint32_t off = (uint32_t)n * 2064 + (uint32_t)k * 2;
        *(uint2*)(sm + RN_WHI + off) = make_uint2(h0, h1);
        *(uint2*)(sm + RN_WLO + off) = make_uint2(l0, l1);
    }
    __syncthreads();

    const uint32_t aFragOff = (uint32_t)(wm + (l & 15)) * 144 + (uint32_t)(l >> 4) * 16;
    const int nloc = wn + (l & 7) + ((l >> 4) << 3);
    const uint32_t bOffH = smb + RN_WHI + (uint32_t)nloc * 2064 + ((l >> 3) & 1) * 16;
    const uint32_t bOffL = bOffH + (RN_WLO - RN_WHI);

    // A staging: per group, 128 threads cover 64 rows x 128B (64B/thread)
    const int gt = tid & 127;
    const int sr = gt >> 1, sq = gt & 1;
    const uint32_t sdstBase = smb + RN_A + (uint32_t)g * 3 * RN_ABUF
                            + (uint32_t)sr * 144 + (uint32_t)sq * 64;
    const int gbar = 1 + g;

    const __half* inp = (LAYER == 0) ? g_inp0 : g_inp1;
    const uint32_t psBase = smb + RN_A;   // partials: [2][64][32] fp32 (reuses A bufs)

    // epilogue thread mapping: 8 outputs per thread
    const int erow = tid >> 2;
    const int ecq  = (tid & 3) * 8;

    for (int t = 0; t < TT; ++t) {
        // prefetch inp[t] (fp16, 16B) early; latency overlaps the MMA phase
        const __half* ip = inp + (size_t)t * BH + (size_t)(m0 + erow) * HH + n0 + ecq;
        uint4 piu = __ldg((const uint4*)ip);

        if (t > 0) {
            const __half* hsrc = (LAYER == 0)
                ? (g_hist + (size_t)(t - 1) * BH)
                : g_h[1 - (t & 1)];
            const __half* gsrc = hsrc + (size_t)(m0 + sr) * HH + g * 512 + sq * 32;

#define RN_STAGE(c, j) do { \
                const __half* p = gsrc + (c) * 64; \
                uint32_t d = sdstBase + (uint32_t)(j) * RN_ABUF; \
                cp16(d, p); cp16(d + 16, p + 8); \
                cp16(d + 32, p + 16); cp16(d + 48, p + 24); \
                CP_COMMIT(); \
            } while (0)

            RN_STAGE(0, 0);
            RN_STAGE(1, 1);

            float acc[2][2][4];
#pragma unroll
            for (int a = 0; a < 2; a++)
#pragma unroll
                for (int b = 0; b < 2; b++)
#pragma unroll
                    for (int c = 0; c < 4; c++) acc[a][b][c] = 0.f;

            for (int c = 0; c < 8; ++c) {
                if (c < 7) { CP_WAIT(1); } else { CP_WAIT(0); }
                BARG(gbar);
                if (c + 2 < 8) RN_STAGE(c + 2, (c + 2) % 3);
                const uint32_t abase = smb + RN_A
                    + (uint32_t)(g * 3 + (c % 3)) * RN_ABUF;
#pragma unroll
                for (int kk = 0; kk < 4; ++kk) {
                    const uint32_t kb = (uint32_t)(g * 512 + c * 64 + kk * 16) * 2;
                    uint32_t a0[4], a1[4], bh[4], bl[4];
                    ldsm4(a0, abase + aFragOff + kk * 32);
                    ldsm4(a1, abase + aFragOff + 2304 + kk * 32);
                    ldsm4(bh, bOffH + kb);
                    ldsm4(bl, bOffL + kb);
                    mma16816(acc[0][0], a0, bh[0], bh[1]);
                    mma16816(acc[0][1], a0, bh[2], bh[3]);
                    mma16816(acc[1][0], a1, bh[0], bh[1]);
                    mma16816(acc[1][1], a1, bh[2], bh[3]);
                    mma16816(acc[0][0], a0, bl[0], bl[1]);
                    mma16816(acc[0][1], a0, bl[2], bl[3]);
                    mma16816(acc[1][0], a1, bl[0], bl[1]);
                    mma16816(acc[1][1], a1, bl[2], bl[3]);
                }
            }
#undef RN_STAGE

            __syncthreads();   // both groups done; A bufs free -> write partials
#pragma unroll
            for (int mc = 0; mc < 2; ++mc)
#pragma unroll
                for (int n8 = 0; n8 < 2; ++n8) {
                    int r = wm + mc * 16 + (l >> 2);
                    int cc = wn + n8 * 8 + (l & 3) * 2;
                    uint32_t pa = psBase + (uint32_t)g * 8192 + (uint32_t)r * 128 + cc * 4;
                    asm volatile("st.shared.v2.f32 [%0], {%1, %2};"
                                 :: "r"(pa), "f"(acc[mc][n8][0]), "f"(acc[mc][n8][1]));
                    asm volatile("st.shared.v2.f32 [%0], {%1, %2};"
                                 :: "r"(pa + 8 * 128), "f"(acc[mc][n8][2]), "f"(acc[mc][n8][3]));
                }
            __syncthreads();
        }

        // --- epilogue: v = tanh(ps0 + ps1 + inp[t]); write fp16 state ---
        {
            float v[8];
            {
                const __half2* ph = (const __half2*)&piu;
#pragma unroll
                for (int j = 0; j < 4; j++) {
                    float2 f = __half22float2(ph[j]);
                    v[2 * j] = f.x; v[2 * j + 1] = f.y;
                }
            }
            if (t > 0) {
                const uint32_t pa = psBase + (uint32_t)erow * 128 + ecq * 4;
                float4 q00, q01, q10, q11;
                asm volatile("ld.shared.v4.f32 {%0,%1,%2,%3}, [%4];"
                             : "=f"(q00.x), "=f"(q00.y), "=f"(q00.z), "=f"(q00.w) : "r"(pa));
                asm volatile("ld.shared.v4.f32 {%0,%1,%2,%3}, [%4];"
                             : "=f"(q01.x), "=f"(q01.y), "=f"(q01.z), "=f"(q01.w) : "r"(pa + 16));
                asm volatile("ld.shared.v4.f32 {%0,%1,%2,%3}, [%4];"
                             : "=f"(q10.x), "=f"(q10.y), "=f"(q10.z), "=f"(q10.w) : "r"(pa + 8192));
                asm volatile("ld.shared.v4.f32 {%0,%1,%2,%3}, [%4];"
                             : "=f"(q11.x), "=f"(q11.y), "=f"(q11.z), "=f"(q11.w) : "r"(pa + 8192 + 16));
                v[0] += q00.x + q10.x; v[1] += q00.y + q10.y;
                v[2] += q00.z + q10.z; v[3] += q00.w + q10.w;
                v[4] += q01.x + q11.x; v[5] += q01.y + q11.y;
                v[6] += q01.z + q11.z; v[7] += q01.w + q11.w;
            }
#pragma unroll
            for (int j = 0; j < 8; j++) v[j] = tanhf(v[j]);
            uint4 u;
            u.x = pack_h2(v[0], v[1]); u.y = pack_h2(v[2], v[3]);
            u.z = pack_h2(v[4], v[5]); u.w = pack_h2(v[6], v[7]);
            const size_t oidx = (size_t)(m0 + erow) * HH + n0 + ecq;
            if (LAYER == 0) {
                *(uint4*)&g_hist[(size_t)t * BH + oidx] = u;
            } else {
                *(uint4*)&g_h[t & 1][oidx] = u;
            }
        }

        group_barrier(mt);
    }
}

// ----------------- final FC + ReLU ---------------------------------------------------
__global__ void __launch_bounds__(256) fc_kernel(
    const float* __restrict__ fcW, const float* __restrict__ fcb,
    float* __restrict__ out)
{
    const int b = blockIdx.x;
    const int tid = threadIdx.x;
    const __half* h = &g_h[1][(size_t)b * HH];   // t=255 -> buffer 1
    float s = 0.f;
    for (int i = tid; i < HH; i += 256) s += __half2float(h[i]) * fcW[i];
#pragma unroll
    for (int o = 16; o; o >>= 1) s += __shfl_xor_sync(0xFFFFFFFFu, s, o);
    __shared__ float red[8];
    if ((tid & 31) == 0) red[tid >> 5] = s;
    __syncthreads();
    if (tid == 0) {
        float tot = 0.f;
#pragma unroll
        for (int i = 0; i < 8; i++) tot += red[i];
        out[b] = fmaxf(tot + fcb[0], 0.f);
    }
}

// ----------------- launch ------------------------------------------------------------
extern "C" void kernel_launch(void* const* d_in, const int* in_sizes, int n_in,
                              void* d_out, int out_size)
{
    const float* x     = (const float*)d_in[0];
    const float* W_ih0 = (const float*)d_in[1];
    const float* W_hh0 = (const float*)d_in[2];
    const float* b_ih0 = (const float*)d_in[3];
    const float* b_hh0 = (const float*)d_in[4];
    const float* W_ih1 = (const float*)d_in[5];
    const float* W_hh1 = (const float*)d_in[6];
    const float* b_ih1 = (const float*)d_in[7];
    const float* b_hh1 = (const float*)d_in[8];
    const float* fc_W  = (const float*)d_in[9];
    const float* fc_b  = (const float*)d_in[10];
    float* out = (float*)d_out;

    cudaFuncSetAttribute(gemm0_f16, cudaFuncAttributeMaxDynamicSharedMemorySize, GM_SMEM);
    cudaFuncSetAttribute(gemm1_f16, cudaFuncAttributeMaxDynamicSharedMemorySize, G1_SMEM);
    cudaFuncSetAttribute(rnn_tc<0>, cudaFuncAttributeMaxDynamicSharedMemorySize, RN_SMEM);
    cudaFuncSetAttribute(rnn_tc<1>, cudaFuncAttributeMaxDynamicSharedMemorySize, RN_SMEM);

    // conversions
    conv_x<<<(TT * BB * II / 4) / 256, 256>>>(x);
    conv_w<0><<<(HH * II / 4 + 255) / 256, 256>>>(W_ih0, HH * II / 4);
    conv_w<1><<<(HH * HH / 4 + 255) / 256, 256>>>(W_ih1, HH * HH / 4);

    dim3 g0grid(HH / 64, (TT * BB) / 128);   // (16, 512)
    gemm0_f16<<<g0grid, 256, GM_SMEM>>>(b_ih0, b_hh0);
    rnn_tc<0><<<128, 256, RN_SMEM>>>(W_hh0);
    dim3 g1grid(HH / 128, (TT * BB) / 128);  // (8, 512)
    gemm1_f16<<<g1grid, 256, G1_SMEM>>>(b_ih1, b_hh1);
    rnn_tc<1><<<128, 256, RN_SMEM>>>(W_hh1);
    fc_kernel<<<BB, 256>>>(fc_W, fc_b, out);
}

// round 9
// speedup vs baseline: 11.5560x; 1.0579x over previous
#include <cuda_runtime.h>
#include <cuda_fp16.h>
#include <math.h>
#include <stdint.h>

#define TT 256
#define BB 256
#define II 256
#define HH 1024
#define BH (BB * HH)

// ----------------- scratch (device globals; no runtime allocation) -----------------
__device__ __half g_inp0[(size_t)TT * BB * HH];      // layer0 preact [T][B][H] fp16
__device__ __half g_inp1[(size_t)TT * BB * HH];      // layer1 preact [T][B][H] fp16
__device__ __half g_x[(size_t)TT * BB * II];         // x transposed [(t*B+b)][i] fp16
__device__ __half g_hist[(size_t)TT * BB * HH];      // layer0 h history fp16
__device__ __half g_w0h[HH * II];                    // W_ih0 hi fp16
__device__ __half g_w0l[HH * II];                    // W_ih0 lo fp16
__device__ __half g_w1h[(size_t)HH * HH];            // W_ih1 hi
__device__ __half g_w1l[(size_t)HH * HH];            // W_ih1 lo
__device__ __half g_h[2][BH];                        // layer1 h ping-pong fp16
__device__ unsigned g_arr[4 * 64];                   // per-mt-group barrier counters

// ----------------- mt-group barrier (32 CTAs per group) -----------------------------
__device__ __forceinline__ void group_barrier(int mt) {
    __syncthreads();
    if (threadIdx.x == 0) {
        __threadfence();
        unsigned* ctr = &g_arr[mt * 64];
        unsigned a = atomicAdd(ctr, 1u) + 1u;
        unsigned target = ((a - 1u) / 32u + 1u) * 32u;
        while (*((volatile unsigned*)ctr) < target) { }
        __threadfence();
    }
    __syncthreads();
}

// ----------------- portable (sm_80+) asm helpers ------------------------------------
__device__ __forceinline__ uint32_t smem_u32(const void* p) {
    uint32_t a;
    asm("{ .reg .u64 t; cvta.to.shared.u64 t, %1; cvt.u32.u64 %0, t; }" : "=r"(a) : "l"(p));
    return a;
}
__device__ __forceinline__ void cp16(uint32_t dst, const void* src) {
    asm volatile("cp.async.cg.shared.global [%0], [%1], 16;" :: "r"(dst), "l"(src));
}
#define CP_COMMIT() asm volatile("cp.async.commit_group;" ::: "memory")
#define CP_WAIT(n)  asm volatile("cp.async.wait_group %0;" :: "n"(n) : "memory")
#define BARG(id)    asm volatile("bar.sync %0, 128;" :: "r"(id) : "memory")

__device__ __forceinline__ void ldsm4(uint32_t* r, uint32_t a) {
    asm volatile("ldmatrix.sync.aligned.m8n8.x4.shared.b16 {%0,%1,%2,%3}, [%4];"
                 : "=r"(r[0]), "=r"(r[1]), "=r"(r[2]), "=r"(r[3]) : "r"(a));
}
__device__ __forceinline__ void mma16816(float* d, const uint32_t* a, uint32_t b0, uint32_t b1) {
    asm volatile(
        "mma.sync.aligned.m16n8k16.row.col.f32.f16.f16.f32 "
        "{%0,%1,%2,%3}, {%4,%5,%6,%7}, {%8,%9}, {%0,%1,%2,%3};"
        : "+f"(d[0]), "+f"(d[1]), "+f"(d[2]), "+f"(d[3])
        : "r"(a[0]), "r"(a[1]), "r"(a[2]), "r"(a[3]), "r"(b0), "r"(b1));
}

__device__ __forceinline__ uint32_t pack_h2(float a, float b) {
    __half2 h = __floats2half2_rn(a, b);
    return *(uint32_t*)&h;
}
__device__ __forceinline__ void split2h(float a, float b, uint32_t& hi, uint32_t& lo) {
    __half ah = __float2half_rn(a), bh = __float2half_rn(b);
    float ra = a - __half2float(ah), rb = b - __half2float(bh);
    hi = (uint32_t)__half_as_ushort(ah) | ((uint32_t)__half_as_ushort(bh) << 16);
    __half al = __float2half_rn(ra), bl = __float2half_rn(rb);
    lo = (uint32_t)__half_as_ushort(al) | ((uint32_t)__half_as_ushort(bl) << 16);
}

// ----------------- conversion kernels ------------------------------------------------
__global__ void __launch_bounds__(256) conv_x(const float* __restrict__ x) {
    int idx = blockIdx.x * 256 + threadIdx.x;      // one float4
    int i4  = idx & (II / 4 - 1);
    int rem = idx >> 6;                             // b*TT + t
    int t = rem & (TT - 1);
    int b = rem >> 8;
    float4 v = ((const float4*)x)[idx];
    uint32_t p0 = pack_h2(v.x, v.y);
    uint32_t p1 = pack_h2(v.z, v.w);
    *(uint2*)&g_x[((size_t)t * BB + b) * II + i4 * 4] = make_uint2(p0, p1);
}

template <int LAYER>
__global__ void __launch_bounds__(256) conv_w(const float* __restrict__ w, int n4) {
    int idx = blockIdx.x * 256 + threadIdx.x;
    if (idx >= n4) return;
    __half* dh = (LAYER == 0) ? g_w0h : g_w1h;
    __half* dl = (LAYER == 0) ? g_w0l : g_w1l;
    float4 v = ((const float4*)w)[idx];
    uint32_t h0, l0, h1, l1;
    split2h(v.x, v.y, h0, l0);
    split2h(v.z, v.w, h1, l1);
    *(uint2*)&dh[(size_t)idx * 4] = make_uint2(h0, h1);
    *(uint2*)&dl[(size_t)idx * 4] = make_uint2(l0, l1);
}

// ----------------- layer0 input GEMM (HMMA fp16, 2-term), CTA 128x64, K=256 --------
#define GM_BUF 20480
#define GM_SMEM (3 * GM_BUF)

__global__ void __launch_bounds__(256) gemm0_f16(
    const float* __restrict__ bia, const float* __restrict__ bib)
{
    constexpr int KD = II;
    constexpr int NC = KD / 32;
    extern __shared__ char sm[];
    const uint32_t smb = smem_u32(sm);
    const int tid = threadIdx.x, wid = tid >> 5, l = tid & 31;
    const int m0 = blockIdx.y * 128, n0 = blockIdx.x * 64;
    const int wm = (wid >> 1) * 32, wn = (wid & 1) * 32;

    const int ar = tid >> 1, ahalf = tid & 1;
    const int br = tid >> 2, bq = tid & 3;
    const __half* gA  = g_x   + (size_t)(m0 + ar) * KD + ahalf * 16;
    const __half* gWh = g_w0h + (size_t)(n0 + br) * KD + bq * 8;
    const __half* gWl = g_w0l + (size_t)(n0 + br) * KD + bq * 8;
    const uint32_t dA  = smb + (uint32_t)ar * 80 + ahalf * 32;
    const uint32_t dBh = smb + 10240 + (uint32_t)br * 80 + bq * 16;

    float acc[2][4][4];
#pragma unroll
    for (int a = 0; a < 2; a++)
#pragma unroll
        for (int b = 0; b < 4; b++)
#pragma unroll
            for (int c = 0; c < 4; c++) acc[a][b][c] = 0.f;

    const uint32_t aFragOff = (uint32_t)(wm + (l & 15)) * 80 + (l >> 4) * 16;
    const int nloc = wn + (l & 7) + ((l >> 4) << 3);
    const uint32_t bFragOff = (uint32_t)nloc * 80 + ((l >> 3) & 1) * 16;

#define GM_STAGE(kc, s) do { \
        uint32_t o = (uint32_t)(s) * GM_BUF; \
        cp16(dA + o, gA + (kc) * 32);           cp16(dA + o + 16, gA + (kc) * 32 + 8); \
        cp16(dBh + o, gWh + (kc) * 32);         cp16(dBh + o + 5120, gWl + (kc) * 32); \
        CP_COMMIT(); \
    } while (0)

    GM_STAGE(0, 0);
    GM_STAGE(1, 1);

    for (int kc = 0; kc < NC; ++kc) {
        if (kc < NC - 1) { CP_WAIT(1); } else { CP_WAIT(0); }
        __syncthreads();
        if (kc + 2 < NC) GM_STAGE(kc + 2, (kc + 2) % 3);
        const uint32_t base = smb + (uint32_t)(kc % 3) * GM_BUF;
#pragma unroll
        for (int kk = 0; kk < 2; ++kk) {
            uint32_t a[2][4];
#pragma unroll
            for (int mc = 0; mc < 2; ++mc)
                ldsm4(a[mc], base + aFragOff + mc * 1280 + kk * 32);
            uint32_t bh[2][4];
#pragma unroll
            for (int nc = 0; nc < 2; ++nc)
                ldsm4(bh[nc], base + 10240 + bFragOff + nc * 1280 + kk * 32);
#pragma unroll
            for (int mc = 0; mc < 2; ++mc)
#pragma unroll
                for (int nc = 0; nc < 2; ++nc) {
                    mma16816(acc[mc][nc * 2 + 0], a[mc], bh[nc][0], bh[nc][1]);
                    mma16816(acc[mc][nc * 2 + 1], a[mc], bh[nc][2], bh[nc][3]);
                }
            uint32_t bl[2][4];
#pragma unroll
            for (int nc = 0; nc < 2; ++nc)
                ldsm4(bl[nc], base + 15360 + bFragOff + nc * 1280 + kk * 32);
#pragma unroll
            for (int mc = 0; mc < 2; ++mc)
#pragma unroll
                for (int nc = 0; nc < 2; ++nc) {
                    mma16816(acc[mc][nc * 2 + 0], a[mc], bl[nc][0], bl[nc][1]);
                    mma16816(acc[mc][nc * 2 + 1], a[mc], bl[nc][2], bl[nc][3]);
                }
        }
    }

#pragma unroll
    for (int mc = 0; mc < 2; ++mc) {
        int r0 = m0 + wm + mc * 16 + (l >> 2);
#pragma unroll
        for (int f = 0; f < 4; ++f) {
            int c = n0 + wn + f * 8 + (l & 3) * 2;
            float bs0 = bia[c] + bib[c];
            float bs1 = bia[c + 1] + bib[c + 1];
            *(uint32_t*)&g_inp0[(size_t)r0 * HH + c] =
                pack_h2(acc[mc][f][0] + bs0, acc[mc][f][1] + bs1);
            *(uint32_t*)&g_inp0[(size_t)(r0 + 8) * HH + c] =
                pack_h2(acc[mc][f][2] + bs0, acc[mc][f][3] + bs1);
        }
    }
#undef GM_STAGE
}

// ----------------- layer1 input GEMM: CTA 128m x 128n, K=1024 ------------------------
#define G1_BUF 30720
#define G1_SMEM (3 * G1_BUF)

__global__ void __launch_bounds__(256) gemm1_f16(
    const float* __restrict__ bia, const float* __restrict__ bib)
{
    constexpr int KD = HH;
    constexpr int NC = KD / 32;   // 32
    extern __shared__ char sm[];
    const uint32_t smb = smem_u32(sm);
    const int tid = threadIdx.x, wid = tid >> 5, l = tid & 31;
    const int m0 = blockIdx.y * 128, n0 = blockIdx.x * 128;
    const int wm = (wid >> 1) * 32, wn = (wid & 1) * 64;

    const int ar = tid >> 1, ahalf = tid & 1;   // 128 rows, 2 thr/row, 32B
    const __half* gA  = g_hist + (size_t)(m0 + ar) * KD + ahalf * 16;
    const __half* gWh = g_w1h + (size_t)(n0 + ar) * KD + ahalf * 16;
    const __half* gWl = g_w1l + (size_t)(n0 + ar) * KD + ahalf * 16;
    const uint32_t dA  = smb + (uint32_t)ar * 80 + ahalf * 32;
    const uint32_t dBh = dA + 10240;
    const uint32_t dBl = dA + 20480;

    float acc[2][8][4];
#pragma unroll
    for (int a = 0; a < 2; a++)
#pragma unroll
        for (int b = 0; b < 8; b++)
#pragma unroll
            for (int c = 0; c < 4; c++) acc[a][b][c] = 0.f;

    const uint32_t aFragOff = (uint32_t)(wm + (l & 15)) * 80 + (l >> 4) * 16;
    const int nloc = wn + (l & 7) + ((l >> 4) << 3);
    const uint32_t bFragOff = (uint32_t)nloc * 80 + ((l >> 3) & 1) * 16;

#define G1_STAGE(kc, s) do { \
        uint32_t o = (uint32_t)(s) * G1_BUF; \
        const __half* pA = gA + (kc) * 32; \
        const __half* pH = gWh + (kc) * 32; \
        const __half* pL = gWl + (kc) * 32; \
        cp16(dA + o, pA);        cp16(dA + o + 16, pA + 8); \
        cp16(dBh + o, pH);       cp16(dBh + o + 16, pH + 8); \
        cp16(dBl + o, pL);       cp16(dBl + o + 16, pL + 8); \
        CP_COMMIT(); \
    } while (0)

    G1_STAGE(0, 0);
    G1_STAGE(1, 1);

    for (int kc = 0; kc < NC; ++kc) {
        if (kc < NC - 1) { CP_WAIT(1); } else { CP_WAIT(0); }
        __syncthreads();
        if (kc + 2 < NC) G1_STAGE(kc + 2, (kc + 2) % 3);
        const uint32_t base = smb + (uint32_t)(kc % 3) * G1_BUF;
#pragma unroll
        for (int kk = 0; kk < 2; ++kk) {
            uint32_t a[2][4];
#pragma unroll
            for (int mc = 0; mc < 2; ++mc)
                ldsm4(a[mc], base + aFragOff + mc * 1280 + kk * 32);
            uint32_t bh[4][4];
#pragma unroll
            for (int nc = 0; nc < 4; ++nc)
                ldsm4(bh[nc], base + 10240 + bFragOff + nc * 1280 + kk * 32);
#pragma unroll
            for (int mc = 0; mc < 2; ++mc)
#pragma unroll
                for (int nc = 0; nc < 4; ++nc) {
                    mma16816(acc[mc][nc * 2 + 0], a[mc], bh[nc][0], bh[nc][1]);
                    mma16816(acc[mc][nc * 2 + 1], a[mc], bh[nc][2], bh[nc][3]);
                }
            uint32_t bl[4][4];
#pragma unroll
            for (int nc = 0; nc < 4; ++nc)
                ldsm4(bl[nc], base + 20480 + bFragOff + nc * 1280 + kk * 32);
#pragma unroll
            for (int mc = 0; mc < 2; ++mc)
#pragma unroll
                for (int nc = 0; nc < 4; ++nc) {
                    mma16816(acc[mc][nc * 2 + 0], a[mc], bl[nc][0], bl[nc][1]);
                    mma16816(acc[mc][nc * 2 + 1], a[mc], bl[nc][2], bl[nc][3]);
                }
        }
    }

#pragma unroll
    for (int mc = 0; mc < 2; ++mc) {
        int r0 = m0 + wm + mc * 16 + (l >> 2);
#pragma unroll
        for (int f = 0; f < 8; ++f) {
            int c = n0 + wn + f * 8 + (l & 3) * 2;
            float bs0 = bia[c] + bib[c];
            float bs1 = bia[c + 1] + bib[c + 1];
            *(uint32_t*)&g_inp1[(size_t)r0 * HH + c] =
                pack_h2(acc[mc][f][0] + bs0, acc[mc][f][1] + bs1);
            *(uint32_t*)&g_inp1[(size_t)(r0 + 8) * HH + c] =
                pack_h2(acc[mc][f][2] + bs0, acc[mc][f][3] + bs1);
        }
    }
#undef G1_STAGE
}

// ----------------- persistent HMMA recurrent kernel (512 threads, 16 warps) ----------
// h_t = tanh(inp[t] + h_{t-1} @ W^T). 128 CTAs = 4 mt(64) x 32 nt(32).
// 16 warps = 4 K-groups (K=256 each) x 4 warps (2m x 2n, warp 32m x 16n).
// W slice [32n][1024k] fp16 hi/lo persistent in smem (stride 2064B).
// A staged per group in 8 chunks of K=32 (5120B buffers, 3 per group).
// 4 partial accumulators reduced via smem.
#define RN_WHI 0
#define RN_WLO 66048
#define RN_A   132096
#define RN_ABUF 5120                      /* chunk: 64 rows x (64B data + 16 pad) */
#define RN_SMEM (RN_A + 12 * RN_ABUF)     /* 193536 */

template <int LAYER>
__global__ void __launch_bounds__(512, 1) rnn_tc(const float* __restrict__ W)
{
    extern __shared__ char sm[];
    const uint32_t smb = smem_u32(sm);
    const int tid = threadIdx.x, wid = tid >> 5, l = tid & 31;
    const int g = wid >> 2;            // K-group 0..3: k in [g*256, g*256+256)
    const int w4 = wid & 3;            // warp within group: 2m x 2n
    const int mt = blockIdx.x >> 5;    // 0..3
    const int nt = blockIdx.x & 31;    // 0..31
    const int m0 = mt * 64, n0 = nt * 32;
    const int wm = (w4 >> 1) * 32, wn = (w4 & 1) * 16;

    // --- W preload: fp32 -> fp16 hi/lo into padded smem [n][k], stride 2064B ---
    for (int i = tid; i < 8192; i += 512) {
        int e = i * 4;
        int n = e >> 10;
        int k = e & 1023;
        float4 w4v = *(const float4*)&W[(size_t)(n0 + n) * HH + k];
        uint32_t h0, l0, h1, l1;
        split2h(w4v.x, w4v.y, h0, l0);
        split2h(w4v.z, w4v.w, h1, l1);
        uint32_t off = (uint32_t)n * 2064 + (uint32_t)k * 2;
        *(uint2*)(sm + RN_WHI + off) = make_uint2(h0, h1);
        *(uint2*)(sm + RN_WLO + off) = make_uint2(l0, l1);
    }
    __syncthreads();

    // fragment addresses (A chunk row stride 80B: 32 k cols x 2B + 16 pad)
    const uint32_t aFragOff = (uint32_t)(wm + (l & 15)) * 80 + (uint32_t)(l >> 4) * 16;
    const int nloc = wn + (l & 7) + ((l >> 4) << 3);
    const uint32_t bOffH = smb + RN_WHI + (uint32_t)nloc * 2064 + ((l >> 3) & 1) * 16;
    const uint32_t bOffL = bOffH + (RN_WLO - RN_WHI);

    // A staging: group's 128 threads cover 64 rows x 64B (2 thr/row, 32B each)
    const int gt = tid & 127;
    const int sr = gt >> 1, sq = gt & 1;
    const uint32_t sdstBase = smb + RN_A + (uint32_t)g * 3 * RN_ABUF
                            + (uint32_t)sr * 80 + (uint32_t)sq * 32;
    const int gbar = 1 + g;

    const __half* inp = (LAYER == 0) ? g_inp0 : g_inp1;
    const uint32_t psBase = smb + RN_A;   // partials: [4][64][32] fp32 = 32KB (reuses A bufs)

    // epilogue thread mapping: 4 outputs per thread (64*32/512)
    const int erow = tid >> 3;
    const int ecq  = (tid & 7) * 4;

    for (int t = 0; t < TT; ++t) {
        // prefetch inp[t] (fp16, 8B) early; latency overlaps the MMA phase
        const __half* ip = inp + (size_t)t * BH + (size_t)(m0 + erow) * HH + n0 + ecq;
        uint2 piu = __ldg((const uint2*)ip);

        if (t > 0) {
            const __half* hsrc = (LAYER == 0)
                ? (g_hist + (size_t)(t - 1) * BH)
                : g_h[1 - (t & 1)];
            // group g, chunk c covers k in [g*256 + c*32, +32)
            const __half* gsrc = hsrc + (size_t)(m0 + sr) * HH + g * 256 + sq * 16;

#define RN_STAGE(c, j) do { \
                const __half* p = gsrc + (c) * 32; \
                uint32_t d = sdstBase + (uint32_t)(j) * RN_ABUF; \
                cp16(d, p); cp16(d + 16, p + 8); \
                CP_COMMIT(); \
            } while (0)

            RN_STAGE(0, 0);
            RN_STAGE(1, 1);

            float acc[2][2][4];
#pragma unroll
            for (int a = 0; a < 2; a++)
#pragma unroll
                for (int b = 0; b < 2; b++)
#pragma unroll
                    for (int c = 0; c < 4; c++) acc[a][b][c] = 0.f;

            for (int c = 0; c < 8; ++c) {
                if (c < 7) { CP_WAIT(1); } else { CP_WAIT(0); }
                BARG(gbar);
                if (c + 2 < 8) RN_STAGE(c + 2, (c + 2) % 3);
                const uint32_t abase = smb + RN_A
                    + (uint32_t)(g * 3 + (c % 3)) * RN_ABUF;
#pragma unroll
                for (int kk = 0; kk < 2; ++kk) {
                    const uint32_t kb = (uint32_t)(g * 256 + c * 32 + kk * 16) * 2;
                    uint32_t a0[4], a1[4], bh[4], bl[4];
                    ldsm4(a0, abase + aFragOff + kk * 32);
                    ldsm4(a1, abase + aFragOff + 1280 + kk * 32);   // +16 rows * 80B
                    ldsm4(bh, bOffH + kb);
                    ldsm4(bl, bOffL + kb);
                    mma16816(acc[0][0], a0, bh[0], bh[1]);
                    mma16816(acc[0][1], a0, bh[2], bh[3]);
                    mma16816(acc[1][0], a1, bh[0], bh[1]);
                    mma16816(acc[1][1], a1, bh[2], bh[3]);
                    mma16816(acc[0][0], a0, bl[0], bl[1]);
                    mma16816(acc[0][1], a0, bl[2], bl[3]);
                    mma16816(acc[1][0], a1, bl[0], bl[1]);
                    mma16816(acc[1][1], a1, bl[2], bl[3]);
                }
            }
#undef RN_STAGE

            __syncthreads();   // all groups done; A bufs free -> write partials
#pragma unroll
            for (int mc = 0; mc < 2; ++mc)
#pragma unroll
                for (int n8 = 0; n8 < 2; ++n8) {
                    int r = wm + mc * 16 + (l >> 2);
                    int cc = wn + n8 * 8 + (l & 3) * 2;
                    uint32_t pa = psBase + (uint32_t)g * 8192 + (uint32_t)r * 128 + cc * 4;
                    asm volatile("st.shared.v2.f32 [%0], {%1, %2};"
                                 :: "r"(pa), "f"(acc[mc][n8][0]), "f"(acc[mc][n8][1]));
                    asm volatile("st.shared.v2.f32 [%0], {%1, %2};"
                                 :: "r"(pa + 8 * 128), "f"(acc[mc][n8][2]), "f"(acc[mc][n8][3]));
                }
            __syncthreads();
        }

        // --- epilogue: v = tanh(sum of 4 partials + inp[t]); write fp16 state ---
        {
            float v[4];
            {
                const __half2* ph = (const __half2*)&piu;
#pragma unroll
                for (int j = 0; j < 2; j++) {
                    float2 f = __half22float2(ph[j]);
                    v[2 * j] = f.x; v[2 * j + 1] = f.y;
                }
            }
            if (t > 0) {
                const uint32_t pa = psBase + (uint32_t)erow * 128 + ecq * 4;
#pragma unroll
                for (int gg = 0; gg < 4; ++gg) {
                    float4 q;
                    asm volatile("ld.shared.v4.f32 {%0,%1,%2,%3}, [%4];"
                                 : "=f"(q.x), "=f"(q.y), "=f"(q.z), "=f"(q.w)
                                 : "r"(pa + gg * 8192));
                    v[0] += q.x; v[1] += q.y; v[2] += q.z; v[3] += q.w;
                }
            }
#pragma unroll
            for (int j = 0; j < 4; j++) v[j] = tanhf(v[j]);
            uint2 u;
            u.x = pack_h2(v[0], v[1]);
            u.y = pack_h2(v[2], v[3]);
            const size_t oidx = (size_t)(m0 + erow) * HH + n0 + ecq;
            if (LAYER == 0) {
                *(uint2*)&g_hist[(size_t)t * BH + oidx] = u;
            } else {
                *(uint2*)&g_h[t & 1][oidx] = u;
            }
        }

        group_barrier(mt);
    }
}

// ----------------- final FC + ReLU ---------------------------------------------------
__global__ void __launch_bounds__(256) fc_kernel(
    const float* __restrict__ fcW, const float* __restrict__ fcb,
    float* __restrict__ out)
{
    const int b = blockIdx.x;
    const int tid = threadIdx.x;
    const __half* h = &g_h[1][(size_t)b * HH];   // t=255 -> buffer 1
    float s = 0.f;
    for (int i = tid; i < HH; i += 256) s += __half2float(h[i]) * fcW[i];
#pragma unroll
    for (int o = 16; o; o >>= 1) s += __shfl_xor_sync(0xFFFFFFFFu, s, o);
    __shared__ float red[8];
    if ((tid & 31) == 0) red[tid >> 5] = s;
    __syncthreads();
    if (tid == 0) {
        float tot = 0.f;
#pragma unroll
        for (int i = 0; i < 8; i++) tot += red[i];
        out[b] = fmaxf(tot + fcb[0], 0.f);
    }
}

// ----------------- launch ------------------------------------------------------------
extern "C" void kernel_launch(void* const* d_in, const int* in_sizes, int n_in,
                              void* d_out, int out_size)
{
    const float* x     = (const float*)d_in[0];
    const float* W_ih0 = (const float*)d_in[1];
    const float* W_hh0 = (const float*)d_in[2];
    const float* b_ih0 = (const float*)d_in[3];
    const float* b_hh0 = (const float*)d_in[4];
    const float* W_ih1 = (const float*)d_in[5];
    const float* W_hh1 = (const float*)d_in[6];
    const float* b_ih1 = (const float*)d_in[7];
    const float* b_hh1 = (const float*)d_in[8];
    const float* fc_W  = (const float*)d_in[9];
    const float* fc_b  = (const float*)d_in[10];
    float* out = (float*)d_out;

    cudaFuncSetAttribute(gemm0_f16, cudaFuncAttributeMaxDynamicSharedMemorySize, GM_SMEM);
    cudaFuncSetAttribute(gemm1_f16, cudaFuncAttributeMaxDynamicSharedMemorySize, G1_SMEM);
    cudaFuncSetAttribute(rnn_tc<0>, cudaFuncAttributeMaxDynamicSharedMemorySize, RN_SMEM);
    cudaFuncSetAttribute(rnn_tc<1>, cudaFuncAttributeMaxDynamicSharedMemorySize, RN_SMEM);

    // conversions
    conv_x<<<(TT * BB * II / 4) / 256, 256>>>(x);
    conv_w<0><<<(HH * II / 4 + 255) / 256, 256>>>(W_ih0, HH * II / 4);
    conv_w<1><<<(HH * HH / 4 + 255) / 256, 256>>>(W_ih1, HH * HH / 4);

    dim3 g0grid(HH / 64, (TT * BB) / 128);   // (16, 512)
    gemm0_f16<<<g0grid, 256, GM_SMEM>>>(b_ih0, b_hh0);
    rnn_tc<0><<<128, 512, RN_SMEM>>>(W_hh0);
    dim3 g1grid(HH / 128, (TT * BB) / 128);  // (8, 512)
    gemm1_f16<<<g1grid, 256, G1_SMEM>>>(b_ih1, b_hh1);
    rnn_tc<1><<<128, 512, RN_SMEM>>>(W_hh1);
    fc_kernel<<<BB, 256>>>(fc_W, fc_b, out);
}

// round 10
// speedup vs baseline: 12.9003x; 1.1163x over previous
#include <cuda_runtime.h>
#include <cuda_fp16.h>
#include <math.h>
#include <stdint.h>

#define TT 256
#define BB 256
#define II 256
#define HH 1024
#define BH (BB * HH)

// ----------------- scratch (device globals; no runtime allocation) -----------------
__device__ __half g_inp0[(size_t)TT * BB * HH];      // layer0 preact [T][B][H] fp16
__device__ __half g_inp1[(size_t)TT * BB * HH];      // layer1 preact [T][B][H] fp16 (from fused proj)
__device__ __half g_x[(size_t)TT * BB * II];         // x transposed [(t*B+b)][i] fp16
__device__ __half g_hist[(size_t)TT * BB * HH];      // layer0 h history fp16
__device__ __half g_w0h[HH * II];                    // W_ih0 hi fp16
__device__ __half g_w0l[HH * II];                    // W_ih0 lo fp16
__device__ __half g_h[2][BH];                        // layer1 h ping-pong fp16
__device__ unsigned g_arr[4 * 64];                   // per-mt-group barrier counters

// ----------------- mt-group barrier (32 CTAs per group) -----------------------------
__device__ __forceinline__ void group_barrier(int mt) {
    __syncthreads();
    if (threadIdx.x == 0) {
        __threadfence();
        unsigned* ctr = &g_arr[mt * 64];
        unsigned a = atomicAdd(ctr, 1u) + 1u;
        unsigned target = ((a - 1u) / 32u + 1u) * 32u;
        while (*((volatile unsigned*)ctr) < target) { }
        __threadfence();
    }
    __syncthreads();
}

// ----------------- portable (sm_80+) asm helpers ------------------------------------
__device__ __forceinline__ uint32_t smem_u32(const void* p) {
    uint32_t a;
    asm("{ .reg .u64 t; cvta.to.shared.u64 t, %1; cvt.u32.u64 %0, t; }" : "=r"(a) : "l"(p));
    return a;
}
__device__ __forceinline__ void cp16(uint32_t dst, const void* src) {
    asm volatile("cp.async.cg.shared.global [%0], [%1], 16;" :: "r"(dst), "l"(src));
}
#define CP_COMMIT() asm volatile("cp.async.commit_group;" ::: "memory")
#define CP_WAIT(n)  asm volatile("cp.async.wait_group %0;" :: "n"(n) : "memory")
#define BARG(id)    asm volatile("bar.sync %0, 128;" :: "r"(id) : "memory")

__device__ __forceinline__ void ldsm4(uint32_t* r, uint32_t a) {
    asm volatile("ldmatrix.sync.aligned.m8n8.x4.shared.b16 {%0,%1,%2,%3}, [%4];"
                 : "=r"(r[0]), "=r"(r[1]), "=r"(r[2]), "=r"(r[3]) : "r"(a));
}
__device__ __forceinline__ void mma16816(float* d, const uint32_t* a, uint32_t b0, uint32_t b1) {
    asm volatile(
        "mma.sync.aligned.m16n8k16.row.col.f32.f16.f16.f32 "
        "{%0,%1,%2,%3}, {%4,%5,%6,%7}, {%8,%9}, {%0,%1,%2,%3};"
        : "+f"(d[0]), "+f"(d[1]), "+f"(d[2]), "+f"(d[3])
        : "r"(a[0]), "r"(a[1]), "r"(a[2]), "r"(a[3]), "r"(b0), "r"(b1));
}

__device__ __forceinline__ uint32_t pack_h2(float a, float b) {
    __half2 h = __floats2half2_rn(a, b);
    return *(uint32_t*)&h;
}
__device__ __forceinline__ void split2h(float a, float b, uint32_t& hi, uint32_t& lo) {
    __half ah = __float2half_rn(a), bh = __float2half_rn(b);
    float ra = a - __half2float(ah), rb = b - __half2float(bh);
    hi = (uint32_t)__half_as_ushort(ah) | ((uint32_t)__half_as_ushort(bh) << 16);
    __half al = __float2half_rn(ra), bl = __float2half_rn(rb);
    lo = (uint32_t)__half_as_ushort(al) | ((uint32_t)__half_as_ushort(bl) << 16);
}

// ----------------- conversion kernels ------------------------------------------------
__global__ void __launch_bounds__(256) conv_x(const float* __restrict__ x) {
    int idx = blockIdx.x * 256 + threadIdx.x;      // one float4
    int i4  = idx & (II / 4 - 1);
    int rem = idx >> 6;                             // b*TT + t
    int t = rem & (TT - 1);
    int b = rem >> 8;
    float4 v = ((const float4*)x)[idx];
    uint32_t p0 = pack_h2(v.x, v.y);
    uint32_t p1 = pack_h2(v.z, v.w);
    *(uint2*)&g_x[((size_t)t * BB + b) * II + i4 * 4] = make_uint2(p0, p1);
}

__global__ void __launch_bounds__(256) conv_w0(const float* __restrict__ w, int n4) {
    int idx = blockIdx.x * 256 + threadIdx.x;
    if (idx >= n4) return;
    float4 v = ((const float4*)w)[idx];
    uint32_t h0, l0, h1, l1;
    split2h(v.x, v.y, h0, l0);
    split2h(v.z, v.w, h1, l1);
    *(uint2*)&g_w0h[(size_t)idx * 4] = make_uint2(h0, h1);
    *(uint2*)&g_w0l[(size_t)idx * 4] = make_uint2(l0, l1);
}

// ----------------- layer0 input GEMM (HMMA fp16, 2-term), CTA 128x64, K=256 --------
#define GM_BUF 20480
#define GM_SMEM (3 * GM_BUF)

__global__ void __launch_bounds__(256) gemm0_f16(
    const float* __restrict__ bia, const float* __restrict__ bib)
{
    constexpr int KD = II;
    constexpr int NC = KD / 32;
    extern __shared__ char sm[];
    const uint32_t smb = smem_u32(sm);
    const int tid = threadIdx.x, wid = tid >> 5, l = tid & 31;
    const int m0 = blockIdx.y * 128, n0 = blockIdx.x * 64;
    const int wm = (wid >> 1) * 32, wn = (wid & 1) * 32;

    const int ar = tid >> 1, ahalf = tid & 1;
    const int br = tid >> 2, bq = tid & 3;
    const __half* gA  = g_x   + (size_t)(m0 + ar) * KD + ahalf * 16;
    const __half* gWh = g_w0h + (size_t)(n0 + br) * KD + bq * 8;
    const __half* gWl = g_w0l + (size_t)(n0 + br) * KD + bq * 8;
    const uint32_t dA  = smb + (uint32_t)ar * 80 + ahalf * 32;
    const uint32_t dBh = smb + 10240 + (uint32_t)br * 80 + bq * 16;

    float acc[2][4][4];
#pragma unroll
    for (int a = 0; a < 2; a++)
#pragma unroll
        for (int b = 0; b < 4; b++)
#pragma unroll
            for (int c = 0; c < 4; c++) acc[a][b][c] = 0.f;

    const uint32_t aFragOff = (uint32_t)(wm + (l & 15)) * 80 + (l >> 4) * 16;
    const int nloc = wn + (l & 7) + ((l >> 4) << 3);
    const uint32_t bFragOff = (uint32_t)nloc * 80 + ((l >> 3) & 1) * 16;

#define GM_STAGE(kc, s) do { \
        uint32_t o = (uint32_t)(s) * GM_BUF; \
        cp16(dA + o, gA + (kc) * 32);           cp16(dA + o + 16, gA + (kc) * 32 + 8); \
        cp16(dBh + o, gWh + (kc) * 32);         cp16(dBh + o + 5120, gWl + (kc) * 32); \
        CP_COMMIT(); \
    } while (0)

    GM_STAGE(0, 0);
    GM_STAGE(1, 1);

    for (int kc = 0; kc < NC; ++kc) {
        if (kc < NC - 1) { CP_WAIT(1); } else { CP_WAIT(0); }
        __syncthreads();
        if (kc + 2 < NC) GM_STAGE(kc + 2, (kc + 2) % 3);
        const uint32_t base = smb + (uint32_t)(kc % 3) * GM_BUF;
#pragma unroll
        for (int kk = 0; kk < 2; ++kk) {
            uint32_t a[2][4];
#pragma unroll
            for (int mc = 0; mc < 2; ++mc)
                ldsm4(a[mc], base + aFragOff + mc * 1280 + kk * 32);
            uint32_t bh[2][4];
#pragma unroll
            for (int nc = 0; nc < 2; ++nc)
                ldsm4(bh[nc], base + 10240 + bFragOff + nc * 1280 + kk * 32);
#pragma unroll
            for (int mc = 0; mc < 2; ++mc)
#pragma unroll
                for (int nc = 0; nc < 2; ++nc) {
                    mma16816(acc[mc][nc * 2 + 0], a[mc], bh[nc][0], bh[nc][1]);
                    mma16816(acc[mc][nc * 2 + 1], a[mc], bh[nc][2], bh[nc][3]);
                }
            uint32_t bl[2][4];
#pragma unroll
            for (int nc = 0; nc < 2; ++nc)
                ldsm4(bl[nc], base + 15360 + bFragOff + nc * 1280 + kk * 32);
#pragma unroll
            for (int mc = 0; mc < 2; ++mc)
#pragma unroll
                for (int nc = 0; nc < 2; ++nc) {
                    mma16816(acc[mc][nc * 2 + 0], a[mc], bl[nc][0], bl[nc][1]);
                    mma16816(acc[mc][nc * 2 + 1], a[mc], bl[nc][2], bl[nc][3]);
                }
        }
    }

#pragma unroll
    for (int mc = 0; mc < 2; ++mc) {
        int r0 = m0 + wm + mc * 16 + (l >> 2);
#pragma unroll
        for (int f = 0; f < 4; ++f) {
            int c = n0 + wn + f * 8 + (l & 3) * 2;
            float bs0 = bia[c] + bib[c];
            float bs1 = bia[c + 1] + bib[c + 1];
            *(uint32_t*)&g_inp0[(size_t)r0 * HH + c] =
                pack_h2(acc[mc][f][0] + bs0, acc[mc][f][1] + bs1);
            *(uint32_t*)&g_inp0[(size_t)(r0 + 8) * HH + c] =
                pack_h2(acc[mc][f][2] + bs0, acc[mc][f][3] + bs1);
        }
    }
#undef GM_STAGE
}

// ----------------- FUSED layer0 recurrence + layer1 input projection -----------------
// Per step t: h0[t] = tanh(inp0[t] + h0[t-1] @ Whh0^T)  (2-term split W)
//             inp1[t-1] = h0[t-1] @ Wih1^T + b  (single fp16 W, reuses staged A!)
// 128 CTAs = 4 mt(64m) x 32 nt(32n); 16 warps = 4 K-groups(K=256) x 4 warps(2m x 2n).
// smem: Whh hi 66048 | Whh lo 66048 | Wih1 66048 | A bufs(24576)/partials(32768) union.
#define F_WHH_H 0
#define F_WHH_L 66048
#define F_WIH   132096
#define F_AREG  198144
#define F_ABUF  3072                       /* k16 chunk: 64 rows x 48B */
#define F_SMEM  230912

__global__ void __launch_bounds__(512, 1) rnn0_fused(
    const float* __restrict__ Whh, const float* __restrict__ Wih,
    const float* __restrict__ bi1, const float* __restrict__ bh1)
{
    extern __shared__ char sm[];
    const uint32_t smb = smem_u32(sm);
    const int tid = threadIdx.x, wid = tid >> 5, l = tid & 31;
    const int g = wid >> 2;            // K-group 0..3: k in [g*256, g*256+256)
    const int w4 = wid & 3;            // warp within group: 2m x 2n
    const int mt = blockIdx.x >> 5;
    const int nt = blockIdx.x & 31;
    const int m0 = mt * 64, n0 = nt * 32;
    const int wm = (w4 >> 1) * 32, wn = (w4 & 1) * 16;

    // --- W_hh preload: fp32 -> fp16 hi/lo [n][k], stride 2064B ---
    for (int i = tid; i < 8192; i += 512) {
        int e = i * 4, n = e >> 10, k = e & 1023;
        float4 wv = *(const float4*)&Whh[(size_t)(n0 + n) * HH + k];
        uint32_t h0, l0, h1, l1;
        split2h(wv.x, wv.y, h0, l0);
        split2h(wv.z, wv.w, h1, l1);
        uint32_t off = (uint32_t)n * 2064 + (uint32_t)k * 2;
        *(uint2*)(sm + F_WHH_H + off) = make_uint2(h0, h1);
        *(uint2*)(sm + F_WHH_L + off) = make_uint2(l0, l1);
    }
    // --- W_ih1 preload: fp32 -> single fp16 [n][k], stride 2064B ---
    for (int i = tid; i < 8192; i += 512) {
        int e = i * 4, n = e >> 10, k = e & 1023;
        float4 wv = *(const float4*)&Wih[(size_t)(n0 + n) * HH + k];
        uint32_t p0 = pack_h2(wv.x, wv.y);
        uint32_t p1 = pack_h2(wv.z, wv.w);
        *(uint2*)(sm + F_WIH + (uint32_t)n * 2064 + (uint32_t)k * 2) = make_uint2(p0, p1);
    }
    __syncthreads();

    // fragment addresses (A chunk row stride 48B: 32B data + 16 pad; conflict-free)
    const uint32_t aFragOff = (uint32_t)(wm + (l & 15)) * 48 + (uint32_t)(l >> 4) * 16;
    const int nloc = wn + (l & 7) + ((l >> 4) << 3);
    const uint32_t bSel = (uint32_t)((l >> 3) & 1) * 16;
    const uint32_t bOffH = smb + F_WHH_H + (uint32_t)nloc * 2064 + bSel;
    const uint32_t bOffL = smb + F_WHH_L + (uint32_t)nloc * 2064 + bSel;
    const uint32_t bOffI = smb + F_WIH   + (uint32_t)nloc * 2064 + bSel;

    // A staging: group's 128 threads cover 64 rows x 32B (2 thr/row, 16B each)
    const int gt = tid & 127;
    const int sr = gt >> 1, sq = gt & 1;
    const uint32_t sdstBase = smb + F_AREG + (uint32_t)g * 2 * F_ABUF
                            + (uint32_t)sr * 48 + (uint32_t)sq * 16;
    const int gbar = 1 + g;
    const uint32_t psBase = smb + F_AREG;   // partials: [4][64][32] fp32 = 32KB

    // epilogue mapping: 4 outputs per thread
    const int erow = tid >> 3;
    const int ecq  = (tid & 7) * 4;
    float pb[4];
#pragma unroll
    for (int j = 0; j < 4; j++)
        pb[j] = __ldg(&bi1[n0 + ecq + j]) + __ldg(&bh1[n0 + ecq + j]);

    for (int t = 0; t <= TT; ++t) {
        const bool hasRec = (t < TT);
        uint2 piu = make_uint2(0u, 0u);
        if (hasRec) {
            const __half* ip = g_inp0 + (size_t)t * BH + (size_t)(m0 + erow) * HH + n0 + ecq;
            piu = __ldg((const uint2*)ip);
        }

        float accr[2][2][4], accp[2][2][4];
        if (t > 0) {
#pragma unroll
            for (int a = 0; a < 2; a++)
#pragma unroll
                for (int b = 0; b < 2; b++)
#pragma unroll
                    for (int c2 = 0; c2 < 4; c2++) { accr[a][b][c2] = 0.f; accp[a][b][c2] = 0.f; }

            const __half* gsrc = g_hist + (size_t)(t - 1) * BH
                               + (size_t)(m0 + sr) * HH + g * 256 + sq * 8;
            // stage chunk 0
            cp16(sdstBase, gsrc);
            CP_COMMIT();

            for (int c = 0; c < 16; ++c) {
                // own copies for chunk c complete:
                CP_WAIT(0);
                // all group threads: chunk c staged AND chunk c-1 consumed:
                BARG(gbar);
                if (c < 15) {
                    cp16(sdstBase + (uint32_t)((c + 1) & 1) * F_ABUF, gsrc + (c + 1) * 16);
                    CP_COMMIT();
                }
                const uint32_t abase = smb + F_AREG + (uint32_t)(g * 2 + (c & 1)) * F_ABUF;
                const uint32_t kb = (uint32_t)(g * 256 + c * 16) * 2;
                uint32_t a0[4], a1[4], bi[4];
                ldsm4(a0, abase + aFragOff);
                ldsm4(a1, abase + aFragOff + 768);
                ldsm4(bi, bOffI + kb);
                if (hasRec) {
                    uint32_t bh[4], bl[4];
                    ldsm4(bh, bOffH + kb);
                    ldsm4(bl, bOffL + kb);
                    mma16816(accr[0][0], a0, bh[0], bh[1]);
                    mma16816(accr[0][1], a0, bh[2], bh[3]);
                    mma16816(accr[1][0], a1, bh[0], bh[1]);
                    mma16816(accr[1][1], a1, bh[2], bh[3]);
                    mma16816(accr[0][0], a0, bl[0], bl[1]);
                    mma16816(accr[0][1], a0, bl[2], bl[3]);
                    mma16816(accr[1][0], a1, bl[0], bl[1]);
                    mma16816(accr[1][1], a1, bl[2], bl[3]);
                }
                mma16816(accp[0][0], a0, bi[0], bi[1]);
                mma16816(accp[0][1], a0, bi[2], bi[3]);
                mma16816(accp[1][0], a1, bi[0], bi[1]);
                mma16816(accp[1][1], a1, bi[2], bi[3]);
            }

            __syncthreads();   // all groups done; A bufs free
            if (hasRec) {
#pragma unroll
                for (int mc = 0; mc < 2; ++mc)
#pragma unroll
                    for (int n8 = 0; n8 < 2; ++n8) {
                        int r = wm + mc * 16 + (l >> 2);
                        int cc = wn + n8 * 8 + (l & 3) * 2;
                        uint32_t pa = psBase + (uint32_t)g * 8192 + (uint32_t)r * 128 + cc * 4;
                        asm volatile("st.shared.v2.f32 [%0], {%1, %2};"
                                     :: "r"(pa), "f"(accr[mc][n8][0]), "f"(accr[mc][n8][1]));
                        asm volatile("st.shared.v2.f32 [%0], {%1, %2};"
                                     :: "r"(pa + 8 * 128), "f"(accr[mc][n8][2]), "f"(accr[mc][n8][3]));
                    }
            }
            __syncthreads();
        }

        // --- rec epilogue: v = tanh(sum partials + inp0[t]); write h0[t] ---
        if (hasRec) {
            float v[4];
            {
                const __half2* ph = (const __half2*)&piu;
#pragma unroll
                for (int j = 0; j < 2; j++) {
                    float2 f = __half22float2(ph[j]);
                    v[2 * j] = f.x; v[2 * j + 1] = f.y;
                }
            }
            if (t > 0) {
                const uint32_t pa = psBase + (uint32_t)erow * 128 + ecq * 4;
#pragma unroll
                for (int gg = 0; gg < 4; ++gg) {
                    float4 q;
                    asm volatile("ld.shared.v4.f32 {%0,%1,%2,%3}, [%4];"
                                 : "=f"(q.x), "=f"(q.y), "=f"(q.z), "=f"(q.w)
                                 : "r"(pa + gg * 8192));
                    v[0] += q.x; v[1] += q.y; v[2] += q.z; v[3] += q.w;
                }
            }
#pragma unroll
            for (int j = 0; j < 4; j++) v[j] = tanhf(v[j]);
            uint2 u;
            u.x = pack_h2(v[0], v[1]);
            u.y = pack_h2(v[2], v[3]);
            *(uint2*)&g_hist[(size_t)t * BH + (size_t)(m0 + erow) * HH + n0 + ecq] = u;

            group_barrier(mt);
        }

        // --- phase B (off inter-CTA critical path): inp1[t-1] = proj + bias ---
        if (t > 0) {
#pragma unroll
            for (int mc = 0; mc < 2; ++mc)
#pragma unroll
                for (int n8 = 0; n8 < 2; ++n8) {
                    int r = wm + mc * 16 + (l >> 2);
                    int cc = wn + n8 * 8 + (l & 3) * 2;
                    uint32_t pa = psBase + (uint32_t)g * 8192 + (uint32_t)r * 128 + cc * 4;
                    asm volatile("st.shared.v2.f32 [%0], {%1, %2};"
                                 :: "r"(pa), "f"(accp[mc][n8][0]), "f"(accp[mc][n8][1]));
                    asm volatile("st.shared.v2.f32 [%0], {%1, %2};"
                                 :: "r"(pa + 8 * 128), "f"(accp[mc][n8][2]), "f"(accp[mc][n8][3]));
                }
            __syncthreads();
            {
                float v[4] = { pb[0], pb[1], pb[2], pb[3] };
                const uint32_t pa = psBase + (uint32_t)erow * 128 + ecq * 4;
#pragma unroll
                for (int gg = 0; gg < 4; ++gg) {
                    float4 q;
                    asm volatile("ld.shared.v4.f32 {%0,%1,%2,%3}, [%4];"
                                 : "=f"(q.x), "=f"(q.y), "=f"(q.z), "=f"(q.w)
                                 : "r"(pa + gg * 8192));
                    v[0] += q.x; v[1] += q.y; v[2] += q.z; v[3] += q.w;
                }
                uint2 u;
                u.x = pack_h2(v[0], v[1]);
                u.y = pack_h2(v[2], v[3]);
                *(uint2*)&g_inp1[(size_t)(t - 1) * BH + (size_t)(m0 + erow) * HH + n0 + ecq] = u;
            }
            __syncthreads();   // partials region free before next step's A staging
        }
    }
}

// ----------------- layer1 recurrence (R9 structure, unchanged) -----------------------
#define RN_WHI 0
#define RN_WLO 66048
#define RN_A   132096
#define RN_ABUF 5120                      /* k32 chunk: 64 rows x 80B */
#define RN_SMEM (RN_A + 12 * RN_ABUF)     /* 193536 */

__global__ void __launch_bounds__(512, 1) rnn1(const float* __restrict__ W)
{
    extern __shared__ char sm[];
    const uint32_t smb = smem_u32(sm);
    const int tid = threadIdx.x, wid = tid >> 5, l = tid & 31;
    const int g = wid >> 2;
    const int w4 = wid & 3;
    const int mt = blockIdx.x >> 5;
    const int nt = blockIdx.x & 31;
    const int m0 = mt * 64, n0 = nt * 32;
    const int wm = (w4 >> 1) * 32, wn = (w4 & 1) * 16;

    for (int i = tid; i < 8192; i += 512) {
        int e = i * 4, n = e >> 10, k = e & 1023;
        float4 w4v = *(const float4*)&W[(size_t)(n0 + n) * HH + k];
        uint32_t h0, l0, h1, l1;
        split2h(w4v.x, w4v.y, h0, l0);
        split2h(w4v.z, w4v.w, h1, l1);
        uint32_t off = (uint32_t)n * 2064 + (uint32_t)k * 2;
        *(uint2*)(sm + RN_WHI + off) = make_uint2(h0, h1);
        *(uint2*)(sm + RN_WLO + off) = make_uint2(l0, l1);
    }
    __syncthreads();

    const uint32_t aFragOff = (uint32_t)(wm + (l & 15)) * 80 + (uint32_t)(l >> 4) * 16;
    const int nloc = wn + (l & 7) + ((l >> 4) << 3);
    const uint32_t bOffH = smb + RN_WHI + (uint32_t)nloc * 2064 + ((l >> 3) & 1) * 16;
    const uint32_t bOffL = bOffH + (RN_WLO - RN_WHI);

    const int gt = tid & 127;
    const int sr = gt >> 1, sq = gt & 1;
    const uint32_t sdstBase = smb + RN_A + (uint32_t)g * 3 * RN_ABUF
                            + (uint32_t)sr * 80 + (uint32_t)sq * 32;
    const int gbar = 1 + g;
    const uint32_t psBase = smb + RN_A;

    const int erow = tid >> 3;
    const int ecq  = (tid & 7) * 4;

    for (int t = 0; t < TT; ++t) {
        const __half* ip = g_inp1 + (size_t)t * BH + (size_t)(m0 + erow) * HH + n0 + ecq;
        uint2 piu = __ldg((const uint2*)ip);

        if (t > 0) {
            const __half* hsrc = g_h[1 - (t & 1)];
            const __half* gsrc = hsrc + (size_t)(m0 + sr) * HH + g * 256 + sq * 16;

#define RN_STAGE(c, j) do { \
                const __half* p = gsrc + (c) * 32; \
                uint32_t d = sdstBase + (uint32_t)(j) * RN_ABUF; \
                cp16(d, p); cp16(d + 16, p + 8); \
                CP_COMMIT(); \
            } while (0)

            RN_STAGE(0, 0);
            RN_STAGE(1, 1);

            float acc[2][2][4];
#pragma unroll
            for (int a = 0; a < 2; a++)
#pragma unroll
                for (int b = 0; b < 2; b++)
#pragma unroll
                    for (int c = 0; c < 4; c++) acc[a][b][c] = 0.f;

            for (int c = 0; c < 8; ++c) {
                if (c < 7) { CP_WAIT(1); } else { CP_WAIT(0); }
                BARG(gbar);
                if (c + 2 < 8) RN_STAGE(c + 2, (c + 2) % 3);
                const uint32_t abase = smb + RN_A
                    + (uint32_t)(g * 3 + (c % 3)) * RN_ABUF;
#pragma unroll
                for (int kk = 0; kk < 2; ++kk) {
                    const uint32_t kb = (uint32_t)(g * 256 + c * 32 + kk * 16) * 2;
                    uint32_t a0[4], a1[4], bh[4], bl[4];
                    ldsm4(a0, abase + aFragOff + kk * 32);
                    ldsm4(a1, abase + aFragOff + 1280 + kk * 32);
                    ldsm4(bh, bOffH + kb);
                    ldsm4(bl, bOffL + kb);
                    mma16816(acc[0][0], a0, bh[0], bh[1]);
                    mma16816(acc[0][1], a0, bh[2], bh[3]);
                    mma16816(acc[1][0], a1, bh[0], bh[1]);
                    mma16816(acc[1][1], a1, bh[2], bh[3]);
                    mma16816(acc[0][0], a0, bl[0], bl[1]);
                    mma16816(acc[0][1], a0, bl[2], bl[3]);
                    mma16816(acc[1][0], a1, bl[0], bl[1]);
                    mma16816(acc[1][1], a1, bl[2], bl[3]);
                }
            }
#undef RN_STAGE

            __syncthreads();
#pragma unroll
            for (int mc = 0; mc < 2; ++mc)
#pragma unroll
                for (int n8 = 0; n8 < 2; ++n8) {
                    int r = wm + mc * 16 + (l >> 2);
                    int cc = wn + n8 * 8 + (l & 3) * 2;
                    uint32_t pa = psBase + (uint32_t)g * 8192 + (uint32_t)r * 128 + cc * 4;
                    asm volatile("st.shared.v2.f32 [%0], {%1, %2};"
                                 :: "r"(pa), "f"(acc[mc][n8][0]), "f"(acc[mc][n8][1]));
                    asm volatile("st.shared.v2.f32 [%0], {%1, %2};"
                                 :: "r"(pa + 8 * 128), "f"(acc[mc][n8][2]), "f"(acc[mc][n8][3]));
                }
            __syncthreads();
        }

        {
            float v[4];
            {
                const __half2* ph = (const __half2*)&piu;
#pragma unroll
                for (int j = 0; j < 2; j++) {
                    float2 f = __half22float2(ph[j]);
                    v[2 * j] = f.x; v[2 * j + 1] = f.y;
                }
            }
            if (t > 0) {
                const uint32_t pa = psBase + (uint32_t)erow * 128 + ecq * 4;
#pragma unroll
                for (int gg = 0; gg < 4; ++gg) {
                    float4 q;
                    asm volatile("ld.shared.v4.f32 {%0,%1,%2,%3}, [%4];"
                                 : "=f"(q.x), "=f"(q.y), "=f"(q.z), "=f"(q.w)
                                 : "r"(pa + gg * 8192));
                    v[0] += q.x; v[1] += q.y; v[2] += q.z; v[3] += q.w;
                }
            }
#pragma unroll
            for (int j = 0; j < 4; j++) v[j] = tanhf(v[j]);
            uint2 u;
            u.x = pack_h2(v[0], v[1]);
            u.y = pack_h2(v[2], v[3]);
            *(uint2*)&g_h[t & 1][(size_t)(m0 + erow) * HH + n0 + ecq] = u;
        }

        group_barrier(mt);
    }
}

// ----------------- final FC + ReLU ---------------------------------------------------
__global__ void __launch_bounds__(256) fc_kernel(
    const float* __restrict__ fcW, const float* __restrict__ fcb,
    float* __restrict__ out)
{
    const int b = blockIdx.x;
    const int tid = threadIdx.x;
    const __half* h = &g_h[1][(size_t)b * HH];   // t=255 -> buffer 1
    float s = 0.f;
    for (int i = tid; i < HH; i += 256) s += __half2float(h[i]) * fcW[i];
#pragma unroll
    for (int o = 16; o; o >>= 1) s += __shfl_xor_sync(0xFFFFFFFFu, s, o);
    __shared__ float red[8];
    if ((tid & 31) == 0) red[tid >> 5] = s;
    __syncthreads();
    if (tid == 0) {
        float tot = 0.f;
#pragma unroll
        for (int i = 0; i < 8; i++) tot += red[i];
        out[b] = fmaxf(tot + fcb[0], 0.f);
    }
}

// ----------------- launch ------------------------------------------------------------
extern "C" void kernel_launch(void* const* d_in, const int* in_sizes, int n_in,
                              void* d_out, int out_size)
{
    const float* x     = (const float*)d_in[0];
    const float* W_ih0 = (const float*)d_in[1];
    const float* W_hh0 = (const float*)d_in[2];
    const float* b_ih0 = (const float*)d_in[3];
    const float* b_hh0 = (const float*)d_in[4];
    const float* W_ih1 = (const float*)d_in[5];
    const float* W_hh1 = (const float*)d_in[6];
    const float* b_ih1 = (const float*)d_in[7];
    const float* b_hh1 = (const float*)d_in[8];
    const float* fc_W  = (const float*)d_in[9];
    const float* fc_b  = (const float*)d_in[10];
    float* out = (float*)d_out;

    cudaFuncSetAttribute(gemm0_f16, cudaFuncAttributeMaxDynamicSharedMemorySize, GM_SMEM);
    cudaFuncSetAttribute(rnn0_fused, cudaFuncAttributeMaxDynamicSharedMemorySize, F_SMEM);
    cudaFuncSetAttribute(rnn1, cudaFuncAttributeMaxDynamicSharedMemorySize, RN_SMEM);

    conv_x<<<(TT * BB * II / 4) / 256, 256>>>(x);
    conv_w0<<<(HH * II / 4 + 255) / 256, 256>>>(W_ih0, HH * II / 4);

    dim3 g0grid(HH / 64, (TT * BB) / 128);   // (16, 512)
    gemm0_f16<<<g0grid, 256, GM_SMEM>>>(b_ih0, b_hh0);
    rnn0_fused<<<128, 512, F_SMEM>>>(W_hh0, W_ih1, b_ih1, b_hh1);
    rnn1<<<128, 512, RN_SMEM>>>(W_hh1);
    fc_kernel<<<BB, 256>>>(fc_W, fc_b, out);
}